// round 4
// baseline (speedup 1.0000x reference)
#include <cuda_runtime.h>
#include <cuda_bf16.h>
#include <math.h>

#define BS 16
#define HDIM 2048
#define QL 768
#define KVL 512
#define DR 64
#define DN 128
#define NH 16
#define NIH 8
#define IDXD 128
#define BLKSZ 128
#define BPS 32
#define MAXKV 4096
#define TOPK 1024
#define NSPLIT 16
#define SPLITROWS 64   /* TOPK / NSPLIT */

#define NZ 8           /* stage1 K-slices */
#define T1DIM 1472     /* 768 + 512 + 64 + 128 */
#define T2DIM 4104     /* 3072 + 1024 + 8 */

#define ATT_SCALE 0.07216878364870323f   /* 1/sqrt(192) */
#define IDX_SCALE 0.08838834764831845f   /* 1/sqrt(128) */

// ---------------- scratch ----------------
__device__ float g_t1p[NZ][BS][T1DIM];
__device__ float g_cq[BS][QL];
__device__ float g_ckv[BS][KVL];
__device__ float g_kr[BS][DR];
__device__ float g_ki[BS][IDXD];
__device__ float g_q[BS][NH * 192];
__device__ float g_qi[BS][NIH * IDXD];
__device__ float g_hw[BS][NIH];
__device__ float g_qpe[BS][NH][DR];
__device__ float g_qlat[BS][NH][KVL];
__device__ float g_isc[BS][MAXKV];
__device__ int   g_sel[BS][TOPK];
__device__ float g_selval[BS][TOPK];
__device__ float g_m[BS][NSPLIT][NH];
__device__ float g_l[BS][NSPLIT][NH];
__device__ float g_op[BS][NSPLIT][NH][KVL];

__device__ __forceinline__ float blockSum256(float v, float* buf) {
    int tid = threadIdx.x;
    buf[tid] = v;
    __syncthreads();
    for (int s = 128; s > 0; s >>= 1) {
        if (tid < s) buf[tid] += buf[tid + s];
        __syncthreads();
    }
    float r = buf[0];
    __syncthreads();
    return r;
}

// ---------------- stage 1: x @ [w_dq | w_dkv_kr | w_idx_k] (partial over K) ----------------
// grid (6 colchunks, 4 batchgroups, 8 k-slices), 256 threads
__global__ void __launch_bounds__(256)
k_stage1(const float* __restrict__ x, const float* __restrict__ w_dq,
         const float* __restrict__ w_dkv, const float* __restrict__ w_idxk) {
    int cx = blockIdx.x, bg = blockIdx.y, z = blockIdx.z;
    int tid = threadIdx.x;
    __shared__ float s_x[4 * 256];
    int i0 = z * 256;
    for (int idx = tid; idx < 4 * 256; idx += 256) {
        int bb = idx >> 8, ii = idx & 255;
        s_x[idx] = x[(bg * 4 + bb) * HDIM + i0 + ii];
    }
    __syncthreads();
    int col = cx * 256 + tid;
    if (col >= T1DIM) return;
    const float* W; int stride, c;
    if (col < QL)                { W = w_dq;   stride = QL;       c = col; }
    else if (col < QL + KVL + DR){ W = w_dkv;  stride = KVL + DR; c = col - QL; }
    else                         { W = w_idxk; stride = IDXD;     c = col - (QL + KVL + DR); }
    const float* wp = W + (size_t)i0 * stride + c;
    float a0 = 0.f, a1 = 0.f, a2 = 0.f, a3 = 0.f;
    #pragma unroll 8
    for (int i = 0; i < 256; i += 4) {
        float w0 = wp[(i + 0) * stride];
        float w1 = wp[(i + 1) * stride];
        float w2 = wp[(i + 2) * stride];
        float w3 = wp[(i + 3) * stride];
        float4 x0 = *(const float4*)&s_x[0 * 256 + i];
        float4 x1 = *(const float4*)&s_x[1 * 256 + i];
        float4 x2 = *(const float4*)&s_x[2 * 256 + i];
        float4 x3 = *(const float4*)&s_x[3 * 256 + i];
        a0 += x0.x * w0 + x0.y * w1 + x0.z * w2 + x0.w * w3;
        a1 += x1.x * w0 + x1.y * w1 + x1.z * w2 + x1.w * w3;
        a2 += x2.x * w0 + x2.y * w1 + x2.z * w2 + x2.w * w3;
        a3 += x3.x * w0 + x3.y * w1 + x3.z * w2 + x3.w * w3;
    }
    int b0 = bg * 4;
    g_t1p[z][b0 + 0][col] = a0;
    g_t1p[z][b0 + 1][col] = a1;
    g_t1p[z][b0 + 2][col] = a2;
    g_t1p[z][b0 + 3][col] = a3;
}

// ---------------- norm1: reduce partials, rmsnorm cq/ckv, rope kr, layernorm ki ----------------
// grid 16, 256 threads
__global__ void __launch_bounds__(256)
k_norm1(const float* __restrict__ gamma_cq, const float* __restrict__ gamma_ckv,
        const float* __restrict__ sinp, const float* __restrict__ cosp,
        const float* __restrict__ in_g, const float* __restrict__ in_b) {
    int b = blockIdx.x, tid = threadIdx.x;
    __shared__ float s_t[T1DIM];
    __shared__ float sred[256];
    for (int i = tid; i < T1DIM; i += 256) {
        float a = 0.f;
        #pragma unroll
        for (int z = 0; z < NZ; z++) a += g_t1p[z][b][i];
        s_t[i] = a;
    }
    __syncthreads();
    // cq rmsnorm
    float ss = 0.f;
    for (int i = tid; i < QL; i += 256) ss += s_t[i] * s_t[i];
    ss = blockSum256(ss, sred);
    float r = rsqrtf(ss / (float)QL + 1e-6f);
    for (int i = tid; i < QL; i += 256) g_cq[b][i] = s_t[i] * r * gamma_cq[i];
    // ckv rmsnorm
    float s2 = 0.f;
    for (int i = tid; i < KVL; i += 256) { float v = s_t[QL + i]; s2 += v * v; }
    s2 = blockSum256(s2, sred);
    float r2 = rsqrtf(s2 / (float)KVL + 1e-6f);
    for (int i = tid; i < KVL; i += 256) g_ckv[b][i] = s_t[QL + i] * r2 * gamma_ckv[i];
    // kr rope
    if (tid < DR) {
        int d = tid;
        float v = s_t[QL + KVL + d];
        float rot = (d < 32) ? -s_t[QL + KVL + d + 32] : s_t[QL + KVL + d - 32];
        g_kr[b][d] = v * cosp[b * DR + d] + rot * sinp[b * DR + d];
    }
    // ki layernorm
    float sm = 0.f;
    for (int i = tid; i < IDXD; i += 256) sm += s_t[QL + KVL + DR + i];
    sm = blockSum256(sm, sred);
    float mean = sm / (float)IDXD;
    float sv = 0.f;
    for (int i = tid; i < IDXD; i += 256) { float c = s_t[QL + KVL + DR + i] - mean; sv += c * c; }
    sv = blockSum256(sv, sred);
    float rv = rsqrtf(sv / (float)IDXD + 1e-6f);
    for (int i = tid; i < IDXD; i += 256) {
        float c = s_t[QL + KVL + DR + i] - mean;
        g_ki[b][i] = c * rv * in_g[i] + in_b[i];
    }
}

// ---------------- stage 2: cq @ [w_uq_qr | w_idx_qb | w_idx_proj] ----------------
// grid (17 colchunks, 4 batchgroups of 4), 256 threads
__global__ void __launch_bounds__(256)
k_stage2(const float* __restrict__ w1, const float* __restrict__ w2,
         const float* __restrict__ w3) {
    int cx = blockIdx.x, bg = blockIdx.y, tid = threadIdx.x;
    __shared__ float s_cq[4 * QL];
    for (int idx = tid; idx < 4 * QL; idx += 256)
        s_cq[idx] = g_cq[bg * 4 + idx / QL][idx % QL];
    __syncthreads();
    int col = cx * 256 + tid;
    if (col >= T2DIM) return;
    const float* W; int stride, c;
    if (col < 3072)      { W = w1; stride = 3072; c = col; }
    else if (col < 4096) { W = w2; stride = 1024; c = col - 3072; }
    else                 { W = w3; stride = 8;    c = col - 4096; }
    const float* wp = W + c;
    float a0 = 0.f, a1 = 0.f, a2 = 0.f, a3 = 0.f;
    #pragma unroll 4
    for (int i = 0; i < QL; i += 4) {
        float w0 = wp[(i + 0) * stride];
        float w1v = wp[(i + 1) * stride];
        float w2v = wp[(i + 2) * stride];
        float w3v = wp[(i + 3) * stride];
        float4 x0 = *(const float4*)&s_cq[0 * QL + i];
        float4 x1 = *(const float4*)&s_cq[1 * QL + i];
        float4 x2 = *(const float4*)&s_cq[2 * QL + i];
        float4 x3 = *(const float4*)&s_cq[3 * QL + i];
        a0 += x0.x * w0 + x0.y * w1v + x0.z * w2v + x0.w * w3v;
        a1 += x1.x * w0 + x1.y * w1v + x1.z * w2v + x1.w * w3v;
        a2 += x2.x * w0 + x2.y * w1v + x2.z * w2v + x2.w * w3v;
        a3 += x3.x * w0 + x3.y * w1v + x3.z * w2v + x3.w * w3v;
    }
    int b0 = bg * 4;
    if (col < 3072) {
        g_q[b0 + 0][col] = a0; g_q[b0 + 1][col] = a1;
        g_q[b0 + 2][col] = a2; g_q[b0 + 3][col] = a3;
    } else if (col < 4096) {
        int cc = col - 3072;
        g_qi[b0 + 0][cc] = a0; g_qi[b0 + 1][cc] = a1;
        g_qi[b0 + 2][cc] = a2; g_qi[b0 + 3][cc] = a3;
    } else {
        int cc = col - 4096;
        g_hw[b0 + 0][cc] = a0; g_hw[b0 + 1][cc] = a1;
        g_hw[b0 + 2][cc] = a2; g_hw[b0 + 3][cc] = a3;
    }
}

// ---------------- q prep: rope q_pe + q_lat[b][h][:] = q_nope[b][h] @ w_uk[h] ----------------
// grid (NH, 4 c-chunks, 4 batchgroups), 128 threads; 4 batch accumulators, d-loop MLP 16
__global__ void __launch_bounds__(128)
k_qprep(const float* __restrict__ w_uk, const float* __restrict__ sinp,
        const float* __restrict__ cosp) {
    int h = blockIdx.x, cc = blockIdx.y, bg = blockIdx.z, tid = threadIdx.x;
    int b0 = bg * 4;
    __shared__ float s_qn[4][DN];
    for (int idx = tid; idx < 4 * DN; idx += 128) {
        int bb = idx >> 7, d = idx & 127;
        s_qn[bb][d] = g_q[b0 + bb][h * 192 + d];
    }
    if (cc == 0) {
        for (int idx = tid; idx < 4 * DR; idx += 128) {
            int bb = idx >> 6, d = idx & 63;
            int b = b0 + bb;
            float v = g_q[b][h * 192 + DN + d];
            float rot = (d < 32) ? -g_q[b][h * 192 + DN + d + 32] : g_q[b][h * 192 + DN + d - 32];
            g_qpe[b][h][d] = v * cosp[b * DR + d] + rot * sinp[b * DR + d];
        }
    }
    __syncthreads();
    int c = cc * 128 + tid;
    const float* wk = w_uk + (size_t)h * DN * KVL + c;
    float a0 = 0.f, a1 = 0.f, a2 = 0.f, a3 = 0.f;
    #pragma unroll 16
    for (int d = 0; d < DN; d++) {
        float w = wk[(size_t)d * KVL];
        a0 += s_qn[0][d] * w;
        a1 += s_qn[1][d] * w;
        a2 += s_qn[2][d] * w;
        a3 += s_qn[3][d] * w;
    }
    g_qlat[b0 + 0][h][c] = a0;
    g_qlat[b0 + 1][h][c] = a1;
    g_qlat[b0 + 2][h][c] = a2;
    g_qlat[b0 + 3][h][c] = a3;
}

// ---------------- index scoring ----------------
// grid (32 chunks, BS), 256 threads; warp processes 2 rows in flight
__global__ void __launch_bounds__(256)
k_iscore(const float* __restrict__ ikc, const int* __restrict__ bt,
         const int* __restrict__ cidx, const int* __restrict__ act_seqs) {
    int chunk = blockIdx.x, b = blockIdx.y, tid = threadIdx.x;
    __shared__ float s_qi[NIH * IDXD];
    __shared__ float s_hw[NIH];
    for (int i = tid; i < NIH * IDXD; i += 256) s_qi[i] = g_qi[b][i];
    if (tid < NIH) s_hw[tid] = g_hw[b][tid];
    __syncthreads();
    int warp = tid >> 5, lane = tid & 31;
    int act = act_seqs[b];
    int ci = cidx[b];
    for (int rr = warp * 2; rr < 128; rr += 16) {
        int n0 = chunk * 128 + rr;
        int n1 = n0 + 1;
        bool v0 = n0 < act, v1 = n1 < act;
        const float* p0;
        const float* p1;
        {
            int blk = bt[b * BPS + (n0 >> 7)];
            long f0 = (long)blk * BLKSZ + (n0 & 127);
            long f1 = f0 + 1;
            p0 = (!v0 || f0 == (long)ci) ? g_ki[b] : ikc + f0 * IDXD;
            p1 = (!v1 || f1 == (long)ci) ? g_ki[b] : ikc + f1 * IDXD;
        }
        float4 kv0 = *(const float4*)(p0 + lane * 4);
        float4 kv1 = *(const float4*)(p1 + lane * 4);
        float acc0[NIH], acc1[NIH];
        #pragma unroll
        for (int h = 0; h < NIH; h++) {
            float4 q = *(const float4*)&s_qi[h * IDXD + lane * 4];
            acc0[h] = kv0.x * q.x + kv0.y * q.y + kv0.z * q.z + kv0.w * q.w;
            acc1[h] = kv1.x * q.x + kv1.y * q.y + kv1.z * q.z + kv1.w * q.w;
        }
        #pragma unroll
        for (int off = 16; off; off >>= 1) {
            #pragma unroll
            for (int h = 0; h < NIH; h++) {
                acc0[h] += __shfl_xor_sync(0xffffffffu, acc0[h], off);
                acc1[h] += __shfl_xor_sync(0xffffffffu, acc1[h], off);
            }
        }
        if (lane == 0) {
            float s0 = 0.f, s1 = 0.f;
            #pragma unroll
            for (int h = 0; h < NIH; h++) {
                s0 += s_hw[h] * fmaxf(acc0[h], 0.f);
                s1 += s_hw[h] * fmaxf(acc1[h], 0.f);
            }
            g_isc[b][n0] = v0 ? s0 * IDX_SCALE : -1e9f;
            g_isc[b][n1] = v1 ? s1 * IDX_SCALE : -1e9f;
        }
    }
}

// ---------------- top-k via radix threshold select (set matches jax ties-by-lowest-index) ----------------
// grid BS, 512 threads. Selection order is arbitrary — attention is permutation-invariant.
__global__ void __launch_bounds__(512)
k_topk(const int* __restrict__ act_seqs) {
    int b = blockIdx.x, tid = threadIdx.x;
    __shared__ unsigned s_key[MAXKV];         // 16 KB ordered keys
    __shared__ unsigned s_hist[256];
    __shared__ unsigned s_bm[MAXKV / 32];     // equality bitmap
    __shared__ unsigned s_cnt;
    __shared__ unsigned s_pref;               // known high bits of threshold
    __shared__ int s_rem, s_Bw, s_need;
    int act = act_seqs[b];
    for (int i = tid; i < MAXKV; i += 512) {
        float v = (i < act) ? g_isc[b][i] : -1e9f;
        unsigned u = __float_as_uint(v);
        u = (u & 0x80000000u) ? ~u : (u | 0x80000000u);
        s_key[i] = u;
    }
    if (tid == 0) { s_cnt = 0; s_rem = TOPK; s_pref = 0; }
    __syncthreads();

    // 4 radix levels (8 bits each, high->low) to find exact threshold key K
    for (int level = 0; level < 4; level++) {
        int shift = 24 - level * 8;
        if (tid < 256) s_hist[tid] = 0;
        __syncthreads();
        unsigned pref = s_pref;
        for (int i = tid; i < MAXKV; i += 512) {
            unsigned u = s_key[i];
            if (level == 0 || (u >> (shift + 8)) == pref)
                atomicAdd(&s_hist[(u >> shift) & 255u], 1u);
        }
        __syncthreads();
        if (tid == 0) {
            int r = s_rem;
            int cum = 0, bsel = 0;
            for (int xb = 255; xb >= 0; xb--) {
                int c = (int)s_hist[xb];
                if (cum + c >= r) { bsel = xb; s_rem = r - cum; break; }
                cum += c;
            }
            s_pref = (s_pref << 8) | (unsigned)bsel;
        }
        __syncthreads();
    }
    unsigned K = s_pref;   // exact threshold key; s_rem = # of ==K to take (lowest indices)

    // select all keys strictly greater than K
    for (int i = tid; i < MAXKV; i += 512) {
        if (s_key[i] > K) {
            unsigned pos = atomicAdd(&s_cnt, 1u);
            g_sel[b][pos] = i;
            g_selval[b][pos] = (i < act) ? g_isc[b][i] : -1e9f;
        }
    }
    // bitmap of ==K, then take s_rem lowest indices
    for (int w = tid; w < MAXKV / 32; w += 512) s_bm[w] = 0;
    __syncthreads();
    for (int i = tid; i < MAXKV; i += 512)
        if (s_key[i] == K) atomicOr(&s_bm[i >> 5], 1u << (i & 31));
    __syncthreads();
    if (tid == 0) {
        int need = s_rem;
        int w = 0;
        for (; w < MAXKV / 32; w++) {
            int pc = __popc(s_bm[w]);
            if (pc >= need) break;
            need -= pc;
        }
        s_Bw = w; s_need = need;
    }
    __syncthreads();
    int Bw = s_Bw, need = s_need;
    for (int i = tid; i < MAXKV; i += 512) {
        if (s_key[i] == K) {
            int w = i >> 5, bit = i & 31;
            bool take = (w < Bw) ||
                        (w == Bw && (int)__popc(s_bm[w] & ((1u << bit) - 1u)) < need);
            if (take) {
                unsigned pos = atomicAdd(&s_cnt, 1u);
                g_sel[b][pos] = i;
                g_selval[b][pos] = (i < act) ? g_isc[b][i] : -1e9f;
            }
        }
    }
}

// ---------------- attention partial (split-KV flash decode) ----------------
// grid (NSPLIT, BS), 512 threads; 64 rows per split
__global__ void __launch_bounds__(512)
k_attn(const float* __restrict__ kvc, const float* __restrict__ krc,
       const int* __restrict__ bt, const int* __restrict__ cidx) {
    int s = blockIdx.x, b = blockIdx.y, tid = threadIdx.x;
    __shared__ float s_qlat[NH * KVL];        // 32 KB
    __shared__ float s_qpe[NH * DR];          //  4 KB
    __shared__ float s_sc[SPLITROWS * NH];    //  4 KB
    __shared__ const float* s_ckvp[SPLITROWS];
    __shared__ const float* s_krp[SPLITROWS];
    __shared__ int s_vld[SPLITROWS];

    const float* qlb = &g_qlat[b][0][0];
    for (int i = tid; i < NH * KVL; i += 512) s_qlat[i] = qlb[i];
    const float* qpb = &g_qpe[b][0][0];
    for (int i = tid; i < NH * DR; i += 512) s_qpe[i] = qpb[i];
    if (tid < SPLITROWS) {
        int j = tid;
        int n = g_sel[b][s * SPLITROWS + j];
        float v = g_selval[b][s * SPLITROWS + j];
        bool valid = v > -1e8f;
        const float* cp; const float* kp;
        if (!valid) { cp = g_ckv[b]; kp = g_kr[b]; }
        else {
            int blk = bt[b * BPS + (n >> 7)];
            long flat = (long)blk * BLKSZ + (n & 127);
            if (flat == (long)cidx[b]) { cp = g_ckv[b]; kp = g_kr[b]; }
            else { cp = kvc + flat * KVL; kp = krc + flat * DR; }
        }
        s_ckvp[j] = cp; s_krp[j] = kp; s_vld[j] = valid ? 1 : 0;
    }
    __syncthreads();

    int warp = tid >> 5, lane = tid & 31;
    // pass 1: scores (each warp: 4 rows)
    for (int j = warp; j < SPLITROWS; j += 16) {
        const float* ckv = s_ckvp[j];
        const float* krp = s_krp[j];
        float acc[NH];
        #pragma unroll
        for (int h = 0; h < NH; h++) acc[h] = 0.f;
        #pragma unroll
        for (int q = 0; q < 4; q++) {
            float4 v = *(const float4*)(ckv + 4 * (lane + 32 * q));
            #pragma unroll
            for (int h = 0; h < NH; h++) {
                float4 ql = *(const float4*)&s_qlat[h * KVL + 4 * (lane + 32 * q)];
                acc[h] += v.x * ql.x + v.y * ql.y + v.z * ql.z + v.w * ql.w;
            }
        }
        float2 kv2 = *(const float2*)(krp + 2 * lane);
        #pragma unroll
        for (int h = 0; h < NH; h++) {
            float2 qp = *(const float2*)&s_qpe[h * DR + 2 * lane];
            acc[h] += kv2.x * qp.x + kv2.y * qp.y;
        }
        #pragma unroll
        for (int off = 16; off; off >>= 1) {
            #pragma unroll
            for (int h = 0; h < NH; h++)
                acc[h] += __shfl_xor_sync(0xffffffffu, acc[h], off);
        }
        if (lane == 0) {
            bool valid = s_vld[j] != 0;
            #pragma unroll
            for (int h = 0; h < NH; h++)
                s_sc[j * NH + h] = valid ? acc[h] * ATT_SCALE : -1e9f;
        }
    }
    __syncthreads();
    // softmax partials: warp h handles head h over 64 rows
    {
        int h = warp;
        float v0 = s_sc[(lane +  0) * NH + h];
        float v1 = s_sc[(lane + 32) * NH + h];
        float m = fmaxf(v0, v1);
        #pragma unroll
        for (int off = 16; off; off >>= 1) m = fmaxf(m, __shfl_xor_sync(0xffffffffu, m, off));
        float e0 = __expf(v0 - m), e1 = __expf(v1 - m);
        s_sc[(lane +  0) * NH + h] = e0;
        s_sc[(lane + 32) * NH + h] = e1;
        float l = e0 + e1;
        #pragma unroll
        for (int off = 16; off; off >>= 1) l += __shfl_xor_sync(0xffffffffu, l, off);
        if (lane == 0) { g_m[b][s][h] = m; g_l[b][s][h] = l; }
    }
    __syncthreads();
    // pass 2: o_part[h][c] = sum_j p[j][h] * ckv[j][c], thread = c, 2-deep prefetch
    {
        int c = tid;
        float acc[NH];
        #pragma unroll
        for (int h = 0; h < NH; h++) acc[h] = 0.f;
        float va = s_ckvp[0][c];
        float vb = s_ckvp[1][c];
        for (int j = 0; j < SPLITROWS; j += 2) {
            float vna = 0.f, vnb = 0.f;
            if (j + 2 < SPLITROWS) { vna = s_ckvp[j + 2][c]; vnb = s_ckvp[j + 3][c]; }
            {
                float4 p0 = *(const float4*)&s_sc[j * NH + 0];
                float4 p1 = *(const float4*)&s_sc[j * NH + 4];
                float4 p2 = *(const float4*)&s_sc[j * NH + 8];
                float4 p3 = *(const float4*)&s_sc[j * NH + 12];
                acc[0]  += p0.x * va; acc[1]  += p0.y * va; acc[2]  += p0.z * va; acc[3]  += p0.w * va;
                acc[4]  += p1.x * va; acc[5]  += p1.y * va; acc[6]  += p1.z * va; acc[7]  += p1.w * va;
                acc[8]  += p2.x * va; acc[9]  += p2.y * va; acc[10] += p2.z * va; acc[11] += p2.w * va;
                acc[12] += p3.x * va; acc[13] += p3.y * va; acc[14] += p3.z * va; acc[15] += p3.w * va;
            }
            {
                float4 p0 = *(const float4*)&s_sc[(j + 1) * NH + 0];
                float4 p1 = *(const float4*)&s_sc[(j + 1) * NH + 4];
                float4 p2 = *(const float4*)&s_sc[(j + 1) * NH + 8];
                float4 p3 = *(const float4*)&s_sc[(j + 1) * NH + 12];
                acc[0]  += p0.x * vb; acc[1]  += p0.y * vb; acc[2]  += p0.z * vb; acc[3]  += p0.w * vb;
                acc[4]  += p1.x * vb; acc[5]  += p1.y * vb; acc[6]  += p1.z * vb; acc[7]  += p1.w * vb;
                acc[8]  += p2.x * vb; acc[9]  += p2.y * vb; acc[10] += p2.z * vb; acc[11] += p2.w * vb;
                acc[12] += p3.x * vb; acc[13] += p3.y * vb; acc[14] += p3.z * vb; acc[15] += p3.w * vb;
            }
            va = vna; vb = vnb;
        }
        #pragma unroll
        for (int h = 0; h < NH; h++) g_op[b][s][h][c] = acc[h];
    }
}

// ---------------- combine splits + project with w_uk ----------------
// grid (NH, BS), 128 threads
__global__ void __launch_bounds__(128)
k_combine(const float* __restrict__ w_uk, float* __restrict__ out) {
    int h = blockIdx.x, b = blockIdx.y, tid = threadIdx.x;
    __shared__ float s_olat[KVL];
    __shared__ float s_w[NSPLIT];
    __shared__ float s_invl;
    if (tid == 0) {
        float M = -1e30f;
        for (int s = 0; s < NSPLIT; s++) M = fmaxf(M, g_m[b][s][h]);
        float L = 0.f;
        for (int s = 0; s < NSPLIT; s++) {
            float w = __expf(g_m[b][s][h] - M);
            s_w[s] = w;
            L += g_l[b][s][h] * w;
        }
        s_invl = 1.f / L;
    }
    __syncthreads();
    for (int c = tid; c < KVL; c += 128) {
        float a = 0.f;
        #pragma unroll
        for (int s = 0; s < NSPLIT; s++) a += g_op[b][s][h][c] * s_w[s];
        s_olat[c] = a * s_invl;
    }
    __syncthreads();
    int d = tid;
    const float* wk = w_uk + ((size_t)(h * DN + d)) * KVL;
    float a = 0.f;
    #pragma unroll 8
    for (int c = 0; c < KVL; c += 4) {
        float4 o4 = *(const float4*)&s_olat[c];
        float4 w4 = *(const float4*)&wk[c];
        a += o4.x * w4.x + o4.y * w4.y + o4.z * w4.z + o4.w * w4.w;
    }
    out[b * (NH * DN) + h * DN + d] = a;
}

// ---------------- launch ----------------
extern "C" void kernel_launch(void* const* d_in, const int* in_sizes, int n_in,
                              void* d_out, int out_size) {
    const float* x            = (const float*)d_in[0];
    const float* w_dq         = (const float*)d_in[1];
    const float* w_uq_qr      = (const float*)d_in[2];
    const float* w_uk         = (const float*)d_in[3];
    const float* w_dkv_kr     = (const float*)d_in[4];
    const float* gamma_cq     = (const float*)d_in[5];
    const float* gamma_ckv    = (const float*)d_in[6];
    const float* sinp         = (const float*)d_in[7];
    const float* cosp         = (const float*)d_in[8];
    const int*   cache_index  = (const int*)d_in[9];
    const float* kv_cache     = (const float*)d_in[10];
    const float* kr_cache     = (const float*)d_in[11];
    const int*   block_table  = (const int*)d_in[12];
    const int*   act_seqs     = (const int*)d_in[13];
    const float* w_idx_qb     = (const float*)d_in[14];
    const float* w_idx_k      = (const float*)d_in[15];
    const float* w_idx_proj   = (const float*)d_in[16];
    const float* in_gamma_k   = (const float*)d_in[17];
    const float* in_beta_k    = (const float*)d_in[18];
    const float* index_k_cache= (const float*)d_in[19];
    float* out = (float*)d_out;

    k_stage1 <<<dim3(6, 4, NZ), 256>>>(x, w_dq, w_dkv_kr, w_idx_k);
    k_norm1  <<<BS, 256>>>(gamma_cq, gamma_ckv, sinp, cosp, in_gamma_k, in_beta_k);
    k_stage2 <<<dim3(17, 4), 256>>>(w_uq_qr, w_idx_qb, w_idx_proj);
    k_qprep  <<<dim3(NH, 4, 4), 128>>>(w_uk, sinp, cosp);
    k_iscore <<<dim3(32, BS), 256>>>(index_k_cache, block_table, cache_index, act_seqs);
    k_topk   <<<BS, 512>>>(act_seqs);
    k_attn   <<<dim3(NSPLIT, BS), 512>>>(kv_cache, kr_cache, block_table, cache_index);
    k_combine<<<dim3(NH, BS), 128>>>(w_uk, out);
}

// round 5
// speedup vs baseline: 1.7248x; 1.7248x over previous
#include <cuda_runtime.h>
#include <cuda_bf16.h>
#include <math.h>

#define BS 16
#define HDIM 2048
#define QL 768
#define KVL 512
#define DR 64
#define DN 128
#define NH 16
#define NIH 8
#define IDXD 128
#define BLKSZ 128
#define BPS 32
#define MAXKV 4096
#define TOPK 1024
#define NSPLIT 16
#define SPLITROWS 64

#define NZ 8
#define T1DIM 1472
#define T2DIM 4104

#define ATT_SCALE 0.07216878364870323f
#define IDX_SCALE 0.08838834764831845f

#define NBMAX 296
#define SMSZ 42240

// ---------------- scratch ----------------
__device__ float g_t1p[NZ][BS][T1DIM];
__device__ float g_cq[BS][QL];
__device__ float g_ckv[BS][KVL];
__device__ float g_kr[BS][DR];
__device__ float g_ki[BS][IDXD];
__device__ float g_q[BS][NH * 192];
__device__ float g_qi[BS][NIH * IDXD];
__device__ float g_hw[BS][NIH];
__device__ float g_qpe[BS][NH][DR];
__device__ float g_qlat[BS][NH][KVL];
__device__ float g_isc[BS][MAXKV];
__device__ int   g_sel[BS][TOPK];
__device__ float g_selval[BS][TOPK];
__device__ float g_m[BS][NSPLIT][NH];
__device__ float g_l[BS][NSPLIT][NH];
__device__ float g_op[BS][NSPLIT][NH][KVL];

// grid barrier state (reset in-kernel before exit)
__device__ unsigned g_barcnt[8];
__device__ unsigned g_ack;

__device__ __forceinline__ void gsync(int id, int nb) {
    __syncthreads();
    if (threadIdx.x == 0) {
        __threadfence();
        atomicAdd(&g_barcnt[id], 1u);
        while (*(volatile unsigned*)&g_barcnt[id] < (unsigned)nb) { __nanosleep(64); }
    }
    __syncthreads();
}

__device__ __forceinline__ float blockSum256(float v, float* buf) {
    int tid = threadIdx.x;
    buf[tid] = v;
    __syncthreads();
    for (int s = 128; s > 0; s >>= 1) {
        if (tid < s) buf[tid] += buf[tid + s];
        __syncthreads();
    }
    float r = buf[0];
    __syncthreads();
    return r;
}

__global__ void __launch_bounds__(256, 2)
k_mega(const float* __restrict__ x, const float* __restrict__ w_dq,
       const float* __restrict__ w_uq_qr, const float* __restrict__ w_uk,
       const float* __restrict__ w_dkv, const float* __restrict__ gamma_cq,
       const float* __restrict__ gamma_ckv, const float* __restrict__ sinp,
       const float* __restrict__ cosp, const int* __restrict__ cidx,
       const float* __restrict__ kvc, const float* __restrict__ krc,
       const int* __restrict__ bt, const int* __restrict__ act_seqs,
       const float* __restrict__ w_idx_qb, const float* __restrict__ w_idxk,
       const float* __restrict__ w_idx_proj, const float* __restrict__ in_g,
       const float* __restrict__ in_b, const float* __restrict__ ikc,
       float* __restrict__ out, int nb)
{
    __shared__ __align__(16) char sm_raw[SMSZ];
    int tid = threadIdx.x;
    int bx = blockIdx.x;

    // ================= P0: stage1 partials x @ [w_dq|w_dkv_kr|w_idx_k] =================
    {
        float* s_x = (float*)sm_raw;   // 4 * 256 floats
        for (int u = bx; u < 192; u += nb) {
            int cx = u % 6, bg = (u / 6) & 3, z = u / 24;
            int i0 = z * 256;
            for (int idx = tid; idx < 4 * 256; idx += 256) {
                int bb = idx >> 8, ii = idx & 255;
                s_x[idx] = x[(bg * 4 + bb) * HDIM + i0 + ii];
            }
            __syncthreads();
            int col = cx * 256 + tid;
            if (col < T1DIM) {
                const float* W; int stride, c;
                if (col < QL)                 { W = w_dq;   stride = QL;       c = col; }
                else if (col < QL + KVL + DR) { W = w_dkv;  stride = KVL + DR; c = col - QL; }
                else                          { W = w_idxk; stride = IDXD;     c = col - (QL + KVL + DR); }
                const float* wp = W + (size_t)i0 * stride + c;
                float a0 = 0.f, a1 = 0.f, a2 = 0.f, a3 = 0.f;
                #pragma unroll 4
                for (int i = 0; i < 256; i += 4) {
                    float w0 = wp[(i + 0) * stride];
                    float w1 = wp[(i + 1) * stride];
                    float w2 = wp[(i + 2) * stride];
                    float w3 = wp[(i + 3) * stride];
                    float4 x0 = *(const float4*)&s_x[0 * 256 + i];
                    float4 x1 = *(const float4*)&s_x[1 * 256 + i];
                    float4 x2 = *(const float4*)&s_x[2 * 256 + i];
                    float4 x3 = *(const float4*)&s_x[3 * 256 + i];
                    a0 += x0.x * w0 + x0.y * w1 + x0.z * w2 + x0.w * w3;
                    a1 += x1.x * w0 + x1.y * w1 + x1.z * w2 + x1.w * w3;
                    a2 += x2.x * w0 + x2.y * w1 + x2.z * w2 + x2.w * w3;
                    a3 += x3.x * w0 + x3.y * w1 + x3.z * w2 + x3.w * w3;
                }
                int b0 = bg * 4;
                g_t1p[z][b0 + 0][col] = a0;
                g_t1p[z][b0 + 1][col] = a1;
                g_t1p[z][b0 + 2][col] = a2;
                g_t1p[z][b0 + 3][col] = a3;
            }
            __syncthreads();
        }
    }
    gsync(0, nb);

    // ================= P1: norms + rope(kr) =================
    {
        float* s_t  = (float*)sm_raw;                   // 1472 floats
        float* sred = (float*)(sm_raw + T1DIM * 4 + 64); // 256 floats
        for (int u = bx; u < BS; u += nb) {
            int b = u;
            for (int i = tid; i < T1DIM; i += 256) {
                float a = 0.f;
                #pragma unroll
                for (int z = 0; z < NZ; z++) a += g_t1p[z][b][i];
                s_t[i] = a;
            }
            __syncthreads();
            float ss = 0.f;
            for (int i = tid; i < QL; i += 256) ss += s_t[i] * s_t[i];
            ss = blockSum256(ss, sred);
            float r = rsqrtf(ss / (float)QL + 1e-6f);
            for (int i = tid; i < QL; i += 256) g_cq[b][i] = s_t[i] * r * gamma_cq[i];
            float s2 = 0.f;
            for (int i = tid; i < KVL; i += 256) { float v = s_t[QL + i]; s2 += v * v; }
            s2 = blockSum256(s2, sred);
            float r2 = rsqrtf(s2 / (float)KVL + 1e-6f);
            for (int i = tid; i < KVL; i += 256) g_ckv[b][i] = s_t[QL + i] * r2 * gamma_ckv[i];
            if (tid < DR) {
                int d = tid;
                float v = s_t[QL + KVL + d];
                float rot = (d < 32) ? -s_t[QL + KVL + d + 32] : s_t[QL + KVL + d - 32];
                g_kr[b][d] = v * cosp[b * DR + d] + rot * sinp[b * DR + d];
            }
            float sm = 0.f;
            for (int i = tid; i < IDXD; i += 256) sm += s_t[QL + KVL + DR + i];
            sm = blockSum256(sm, sred);
            float mean = sm / (float)IDXD;
            float sv = 0.f;
            for (int i = tid; i < IDXD; i += 256) { float c = s_t[QL + KVL + DR + i] - mean; sv += c * c; }
            sv = blockSum256(sv, sred);
            float rv = rsqrtf(sv / (float)IDXD + 1e-6f);
            for (int i = tid; i < IDXD; i += 256) {
                float c = s_t[QL + KVL + DR + i] - mean;
                g_ki[b][i] = c * rv * in_g[i] + in_b[i];
            }
            __syncthreads();
        }
    }
    gsync(1, nb);

    // ================= P2: stage2 cq @ [w_uq_qr|w_idx_qb|w_idx_proj], 2 batches/unit =================
    {
        float* s_cq = (float*)sm_raw;  // 2 * 768 floats
        for (int u = bx; u < 17 * 8; u += nb) {
            int cx = u % 17, bg = u / 17;
            for (int idx = tid; idx < 2 * QL; idx += 256)
                s_cq[idx] = g_cq[bg * 2 + idx / QL][idx % QL];
            __syncthreads();
            int col = cx * 256 + tid;
            if (col < T2DIM) {
                const float* W; int stride, c;
                if (col < 3072)      { W = w_uq_qr;    stride = 3072; c = col; }
                else if (col < 4096) { W = w_idx_qb;   stride = 1024; c = col - 3072; }
                else                 { W = w_idx_proj; stride = 8;    c = col - 4096; }
                const float* wp = W + c;
                float a0 = 0.f, a1 = 0.f;
                #pragma unroll 4
                for (int i = 0; i < QL; i += 4) {
                    float w0  = wp[(i + 0) * stride];
                    float w1v = wp[(i + 1) * stride];
                    float w2v = wp[(i + 2) * stride];
                    float w3v = wp[(i + 3) * stride];
                    float4 x0 = *(const float4*)&s_cq[0 * QL + i];
                    float4 x1 = *(const float4*)&s_cq[1 * QL + i];
                    a0 += x0.x * w0 + x0.y * w1v + x0.z * w2v + x0.w * w3v;
                    a1 += x1.x * w0 + x1.y * w1v + x1.z * w2v + x1.w * w3v;
                }
                int b0 = bg * 2;
                if (col < 3072) {
                    g_q[b0 + 0][col] = a0; g_q[b0 + 1][col] = a1;
                } else if (col < 4096) {
                    int cc = col - 3072;
                    g_qi[b0 + 0][cc] = a0; g_qi[b0 + 1][cc] = a1;
                } else {
                    int cc = col - 4096;
                    g_hw[b0 + 0][cc] = a0; g_hw[b0 + 1][cc] = a1;
                }
            }
            __syncthreads();
        }
    }
    gsync(2, nb);

    // ================= P3: qprep (128 units) + iscore (512 units) =================
    {
        for (int u = bx; u < 128 + 512; u += nb) {
            if (u < 128) {
                // qprep: h, cc (2 chunks of 256), bg (4 groups of 4)
                int h = u & 15, r = u >> 4;
                int cc = r & 1, bg = r >> 1;
                int b0 = bg * 4;
                float* s_qn = (float*)sm_raw;  // [4][128]
                for (int idx = tid; idx < 512; idx += 256)
                    s_qn[idx] = g_q[b0 + (idx >> 7)][h * 192 + (idx & 127)];
                if (cc == 0) {
                    int bb = tid >> 6, d = tid & 63;
                    int b = b0 + bb;
                    float v = g_q[b][h * 192 + DN + d];
                    float rot = (d < 32) ? -g_q[b][h * 192 + DN + d + 32] : g_q[b][h * 192 + DN + d - 32];
                    g_qpe[b][h][d] = v * cosp[b * DR + d] + rot * sinp[b * DR + d];
                }
                __syncthreads();
                int c = cc * 256 + tid;
                const float* wk = w_uk + (size_t)h * DN * KVL + c;
                float a0 = 0.f, a1 = 0.f, a2 = 0.f, a3 = 0.f;
                #pragma unroll 16
                for (int d = 0; d < DN; d++) {
                    float w = wk[(size_t)d * KVL];
                    a0 += s_qn[0 * 128 + d] * w;
                    a1 += s_qn[1 * 128 + d] * w;
                    a2 += s_qn[2 * 128 + d] * w;
                    a3 += s_qn[3 * 128 + d] * w;
                }
                g_qlat[b0 + 0][h][c] = a0;
                g_qlat[b0 + 1][h][c] = a1;
                g_qlat[b0 + 2][h][c] = a2;
                g_qlat[b0 + 3][h][c] = a3;
                __syncthreads();
            } else {
                // iscore
                int u2 = u - 128;
                int chunk = u2 & 31, b = u2 >> 5;
                float* s_qi = (float*)sm_raw;                  // 1024 floats
                float* s_hw = (float*)(sm_raw + 4096);         // 8 floats
                for (int i = tid; i < NIH * IDXD; i += 256) s_qi[i] = g_qi[b][i];
                if (tid < NIH) s_hw[tid] = g_hw[b][tid];
                __syncthreads();
                int warp = tid >> 5, lane = tid & 31;
                int act = act_seqs[b];
                int ci = cidx[b];
                for (int r = warp; r < 128; r += 8) {
                    int n = chunk * 128 + r;
                    if (n >= act) { if (lane == 0) g_isc[b][n] = -1e9f; continue; }
                    int blk = bt[b * BPS + (n >> 7)];
                    long flat = (long)blk * BLKSZ + (n & 127);
                    const float* kr = (flat == (long)ci) ? g_ki[b] : ikc + flat * IDXD;
                    float4 kv = *(const float4*)(kr + lane * 4);
                    float acc[NIH];
                    #pragma unroll
                    for (int h = 0; h < NIH; h++) {
                        float4 q = *(const float4*)&s_qi[h * IDXD + lane * 4];
                        acc[h] = kv.x * q.x + kv.y * q.y + kv.z * q.z + kv.w * q.w;
                    }
                    #pragma unroll
                    for (int off = 16; off; off >>= 1) {
                        #pragma unroll
                        for (int h = 0; h < NIH; h++)
                            acc[h] += __shfl_xor_sync(0xffffffffu, acc[h], off);
                    }
                    if (lane == 0) {
                        float s = 0.f;
                        #pragma unroll
                        for (int h = 0; h < NIH; h++) s += s_hw[h] * fmaxf(acc[h], 0.f);
                        g_isc[b][n] = s * IDX_SCALE;
                    }
                }
                __syncthreads();
            }
        }
    }
    gsync(3, nb);

    // ================= P4: top-k radix threshold select =================
    {
        unsigned* s_key  = (unsigned*)sm_raw;               // 4096
        unsigned* s_hist = (unsigned*)(sm_raw + 16384);     // 256
        unsigned* s_scan = (unsigned*)(sm_raw + 17408);     // 256
        unsigned* s_bm   = (unsigned*)(sm_raw + 18432);     // 128
        unsigned* s_cnt  = (unsigned*)(sm_raw + 18944);
        unsigned* s_pref = (unsigned*)(sm_raw + 18948);
        int*      s_rem  = (int*)(sm_raw + 18952);
        int*      s_Bw   = (int*)(sm_raw + 18956);
        int*      s_need = (int*)(sm_raw + 18960);
        for (int u = bx; u < BS; u += nb) {
            int b = u;
            int act = act_seqs[b];
            for (int i = tid; i < MAXKV; i += 256) {
                float v = (i < act) ? g_isc[b][i] : -1e9f;
                unsigned uu = __float_as_uint(v);
                uu = (uu & 0x80000000u) ? ~uu : (uu | 0x80000000u);
                s_key[i] = uu;
            }
            if (tid == 0) { *s_cnt = 0; *s_rem = TOPK; *s_pref = 0; }
            __syncthreads();
            for (int level = 0; level < 4; level++) {
                int shift = 24 - level * 8;
                s_hist[tid] = 0;
                __syncthreads();
                unsigned pref = *s_pref;
                for (int i = tid; i < MAXKV; i += 256) {
                    unsigned uu = s_key[i];
                    if (level == 0 || (uu >> (shift + 8)) == pref)
                        atomicAdd(&s_hist[(uu >> shift) & 255u], 1u);
                }
                __syncthreads();
                // inclusive suffix scan of hist
                s_scan[tid] = s_hist[tid];
                __syncthreads();
                #pragma unroll
                for (int off = 1; off < 256; off <<= 1) {
                    unsigned t = (tid + off < 256) ? s_scan[tid + off] : 0u;
                    __syncthreads();
                    s_scan[tid] += t;
                    __syncthreads();
                }
                int rem = *s_rem;
                unsigned cumGT = s_scan[tid] - s_hist[tid];
                if ((int)cumGT < rem && (int)s_scan[tid] >= rem) {
                    *s_pref = (pref << 8) | (unsigned)tid;
                    *s_rem = rem - (int)cumGT;
                }
                __syncthreads();
            }
            unsigned K = *s_pref;
            for (int i = tid; i < MAXKV; i += 256) {
                if (s_key[i] > K) {
                    unsigned pos = atomicAdd(s_cnt, 1u);
                    g_sel[b][pos] = i;
                    g_selval[b][pos] = (i < act) ? g_isc[b][i] : -1e9f;
                }
            }
            for (int w = tid; w < MAXKV / 32; w += 256) s_bm[w] = 0;
            __syncthreads();
            for (int i = tid; i < MAXKV; i += 256)
                if (s_key[i] == K) atomicOr(&s_bm[i >> 5], 1u << (i & 31));
            __syncthreads();
            if (tid == 0) {
                int need = *s_rem;
                int w = 0;
                for (; w < MAXKV / 32; w++) {
                    int pc = __popc(s_bm[w]);
                    if (pc >= need) break;
                    need -= pc;
                }
                *s_Bw = w; *s_need = need;
            }
            __syncthreads();
            int Bw = *s_Bw, need = *s_need;
            for (int i = tid; i < MAXKV; i += 256) {
                if (s_key[i] == K) {
                    int w = i >> 5, bit = i & 31;
                    bool take = (w < Bw) ||
                                (w == Bw && (int)__popc(s_bm[w] & ((1u << bit) - 1u)) < need);
                    if (take) {
                        unsigned pos = atomicAdd(s_cnt, 1u);
                        g_sel[b][pos] = i;
                        g_selval[b][pos] = (i < act) ? g_isc[b][i] : -1e9f;
                    }
                }
            }
            __syncthreads();
        }
    }
    gsync(4, nb);

    // ================= P5: attention partials =================
    {
        float* s_qlat = (float*)sm_raw;                       // 8192 floats
        float* s_qpe  = (float*)(sm_raw + 32768);             // 1024 floats
        float* s_sc   = (float*)(sm_raw + 36864);             // 1024 floats
        const float** s_ckvp = (const float**)(sm_raw + 40960);  // 64 ptrs
        const float** s_krp  = (const float**)(sm_raw + 41472);  // 64 ptrs
        int* s_vld = (int*)(sm_raw + 41984);                   // 64 ints
        for (int u = bx; u < NSPLIT * BS; u += nb) {
            int s = u & 15, b = u >> 4;
            const float* qlb = &g_qlat[b][0][0];
            for (int i = tid; i < NH * KVL; i += 256) s_qlat[i] = qlb[i];
            const float* qpb = &g_qpe[b][0][0];
            for (int i = tid; i < NH * DR; i += 256) s_qpe[i] = qpb[i];
            if (tid < SPLITROWS) {
                int j = tid;
                int n = g_sel[b][s * SPLITROWS + j];
                float v = g_selval[b][s * SPLITROWS + j];
                bool valid = v > -1e8f;
                const float* cp; const float* kp;
                if (!valid) { cp = g_ckv[b]; kp = g_kr[b]; }
                else {
                    int blk = bt[b * BPS + (n >> 7)];
                    long flat = (long)blk * BLKSZ + (n & 127);
                    if (flat == (long)cidx[b]) { cp = g_ckv[b]; kp = g_kr[b]; }
                    else { cp = kvc + flat * KVL; kp = krc + flat * DR; }
                }
                s_ckvp[j] = cp; s_krp[j] = kp; s_vld[j] = valid ? 1 : 0;
            }
            __syncthreads();
            int warp = tid >> 5, lane = tid & 31;
            // pass 1: scores, 8 warps x 8 rows
            for (int j = warp; j < SPLITROWS; j += 8) {
                const float* ckv = s_ckvp[j];
                const float* krp = s_krp[j];
                float acc[NH];
                #pragma unroll
                for (int h = 0; h < NH; h++) acc[h] = 0.f;
                #pragma unroll
                for (int q = 0; q < 4; q++) {
                    float4 v = *(const float4*)(ckv + 4 * (lane + 32 * q));
                    #pragma unroll
                    for (int h = 0; h < NH; h++) {
                        float4 ql = *(const float4*)&s_qlat[h * KVL + 4 * (lane + 32 * q)];
                        acc[h] += v.x * ql.x + v.y * ql.y + v.z * ql.z + v.w * ql.w;
                    }
                }
                float2 kv2 = *(const float2*)(krp + 2 * lane);
                #pragma unroll
                for (int h = 0; h < NH; h++) {
                    float2 qp = *(const float2*)&s_qpe[h * DR + 2 * lane];
                    acc[h] += kv2.x * qp.x + kv2.y * qp.y;
                }
                #pragma unroll
                for (int off = 16; off; off >>= 1) {
                    #pragma unroll
                    for (int h = 0; h < NH; h++)
                        acc[h] += __shfl_xor_sync(0xffffffffu, acc[h], off);
                }
                if (lane == 0) {
                    bool valid = s_vld[j] != 0;
                    #pragma unroll
                    for (int h = 0; h < NH; h++)
                        s_sc[j * NH + h] = valid ? acc[h] * ATT_SCALE : -1e9f;
                }
            }
            __syncthreads();
            // softmax partials: 8 warps, 2 heads each
            for (int h = warp; h < NH; h += 8) {
                float v0 = s_sc[(lane +  0) * NH + h];
                float v1 = s_sc[(lane + 32) * NH + h];
                float m = fmaxf(v0, v1);
                #pragma unroll
                for (int off = 16; off; off >>= 1) m = fmaxf(m, __shfl_xor_sync(0xffffffffu, m, off));
                float e0 = __expf(v0 - m), e1 = __expf(v1 - m);
                s_sc[(lane +  0) * NH + h] = e0;
                s_sc[(lane + 32) * NH + h] = e1;
                float l = e0 + e1;
                #pragma unroll
                for (int off = 16; off; off >>= 1) l += __shfl_xor_sync(0xffffffffu, l, off);
                if (lane == 0) { g_m[b][s][h] = m; g_l[b][s][h] = l; }
            }
            __syncthreads();
            // pass 2: o_part, two c-halves of 256
            #pragma unroll
            for (int half = 0; half < 2; half++) {
                int c = half * 256 + tid;
                float acc[NH];
                #pragma unroll
                for (int h = 0; h < NH; h++) acc[h] = 0.f;
                #pragma unroll 4
                for (int j = 0; j < SPLITROWS; j++) {
                    float v = s_ckvp[j][c];
                    float4 p0 = *(const float4*)&s_sc[j * NH + 0];
                    float4 p1 = *(const float4*)&s_sc[j * NH + 4];
                    float4 p2 = *(const float4*)&s_sc[j * NH + 8];
                    float4 p3 = *(const float4*)&s_sc[j * NH + 12];
                    acc[0]  += p0.x * v; acc[1]  += p0.y * v; acc[2]  += p0.z * v; acc[3]  += p0.w * v;
                    acc[4]  += p1.x * v; acc[5]  += p1.y * v; acc[6]  += p1.z * v; acc[7]  += p1.w * v;
                    acc[8]  += p2.x * v; acc[9]  += p2.y * v; acc[10] += p2.z * v; acc[11] += p2.w * v;
                    acc[12] += p3.x * v; acc[13] += p3.y * v; acc[14] += p3.z * v; acc[15] += p3.w * v;
                }
                #pragma unroll
                for (int h = 0; h < NH; h++) g_op[b][s][h][c] = acc[h];
            }
            __syncthreads();
        }
    }
    gsync(5, nb);

    // ================= P6: combine + output projection =================
    {
        float* s_olat = (float*)sm_raw;              // 512 floats
        float* s_w    = (float*)(sm_raw + 2048);     // 16 floats
        float* s_invl = (float*)(sm_raw + 2112);
        for (int u = bx; u < NH * BS; u += nb) {
            int h = u & 15, b = u >> 4;
            if (tid == 0) {
                float M = -1e30f;
                for (int s = 0; s < NSPLIT; s++) M = fmaxf(M, g_m[b][s][h]);
                float L = 0.f;
                for (int s = 0; s < NSPLIT; s++) {
                    float w = __expf(g_m[b][s][h] - M);
                    s_w[s] = w;
                    L += g_l[b][s][h] * w;
                }
                *s_invl = 1.f / L;
            }
            __syncthreads();
            for (int c = tid; c < KVL; c += 256) {
                float a = 0.f;
                #pragma unroll
                for (int s = 0; s < NSPLIT; s++) a += g_op[b][s][h][c] * s_w[s];
                s_olat[c] = a * (*s_invl);
            }
            __syncthreads();
            if (tid < DN) {
                int d = tid;
                const float* wk = w_uk + ((size_t)(h * DN + d)) * KVL;
                float a = 0.f;
                #pragma unroll 8
                for (int c = 0; c < KVL; c += 4) {
                    float4 o4 = *(const float4*)&s_olat[c];
                    float4 w4 = *(const float4*)&wk[c];
                    a += o4.x * w4.x + o4.y * w4.y + o4.z * w4.z + o4.w * w4.w;
                }
                out[b * (NH * DN) + h * DN + d] = a;
            }
            __syncthreads();
        }
    }
    gsync(6, nb);

    // reset barrier state for next graph replay (ack ensures no block still spins)
    if (tid == 0) {
        __threadfence();
        unsigned a = atomicAdd(&g_ack, 1u) + 1;
        if (a == (unsigned)nb) {
            #pragma unroll
            for (int i = 0; i < 8; i++) g_barcnt[i] = 0;
            g_ack = 0;
            __threadfence();
        }
    }
}

// ---------------- launch ----------------
extern "C" void kernel_launch(void* const* d_in, const int* in_sizes, int n_in,
                              void* d_out, int out_size) {
    const float* x            = (const float*)d_in[0];
    const float* w_dq         = (const float*)d_in[1];
    const float* w_uq_qr      = (const float*)d_in[2];
    const float* w_uk         = (const float*)d_in[3];
    const float* w_dkv_kr     = (const float*)d_in[4];
    const float* gamma_cq     = (const float*)d_in[5];
    const float* gamma_ckv    = (const float*)d_in[6];
    const float* sinp         = (const float*)d_in[7];
    const float* cosp         = (const float*)d_in[8];
    const int*   cache_index  = (const int*)d_in[9];
    const float* kv_cache     = (const float*)d_in[10];
    const float* kr_cache     = (const float*)d_in[11];
    const int*   block_table  = (const int*)d_in[12];
    const int*   act_seqs     = (const int*)d_in[13];
    const float* w_idx_qb     = (const float*)d_in[14];
    const float* w_idx_k      = (const float*)d_in[15];
    const float* w_idx_proj   = (const float*)d_in[16];
    const float* in_gamma_k   = (const float*)d_in[17];
    const float* in_beta_k    = (const float*)d_in[18];
    const float* index_k_cache= (const float*)d_in[19];
    float* out = (float*)d_out;

    int sms = 148, bpm = 0;
    cudaDeviceGetAttribute(&sms, cudaDevAttrMultiProcessorCount, 0);
    cudaOccupancyMaxActiveBlocksPerMultiprocessor(&bpm, k_mega, 256, 0);
    if (bpm < 1) bpm = 1;
    int nb = bpm * sms;
    if (nb > NBMAX) nb = NBMAX;

    k_mega<<<nb, 256>>>(x, w_dq, w_uq_qr, w_uk, w_dkv_kr, gamma_cq, gamma_ckv,
                        sinp, cosp, cache_index, kv_cache, kr_cache, block_table,
                        act_seqs, w_idx_qb, w_idx_k, w_idx_proj, in_gamma_k,
                        in_beta_k, index_k_cache, out, nb);
}

// round 6
// speedup vs baseline: 1.7511x; 1.0153x over previous
#include <cuda_runtime.h>
#include <cuda_bf16.h>
#include <math.h>

#define BS 16
#define HDIM 2048
#define QL 768
#define KVL 512
#define DR 64
#define DN 128
#define NH 16
#define NIH 8
#define IDXD 128
#define BLKSZ 128
#define BPS 32
#define MAXKV 4096
#define TOPK 1024
#define NSPLIT 16
#define SPLITROWS 64

#define NZ1 16          /* stage1 K-slices of 128 */
#define NZ2 16          /* stage2 K-slices of 48 */
#define T1DIM 1472
#define T2DIM 4104

#define ATT_SCALE 0.07216878364870323f
#define IDX_SCALE 0.08838834764831845f

#define NBMAX 296
#define SMSZ 42240

// ---------------- scratch ----------------
__device__ float g_t1p[NZ1][BS][T1DIM];
__device__ float g_t2p[NZ2][BS][T2DIM];
__device__ float g_cq[BS][QL];
__device__ float g_ckv[BS][KVL];
__device__ float g_kr[BS][DR];
__device__ float g_ki[BS][IDXD];
__device__ float g_q[BS][NH * 192];
__device__ float g_qi[BS][NIH * IDXD];
__device__ float g_hw[BS][NIH];
__device__ float g_qpe[BS][NH][DR];
__device__ float g_qlat[BS][NH][KVL];
__device__ float g_isc[BS][MAXKV];
__device__ int   g_sel[BS][TOPK];
__device__ float g_selval[BS][TOPK];
__device__ float g_m[BS][NSPLIT][NH];
__device__ float g_l[BS][NSPLIT][NH];
__device__ float g_op[BS][NSPLIT][NH][KVL];

// grid barrier state (reset in-kernel before exit)
__device__ unsigned g_barcnt[16];
__device__ unsigned g_ack;

__device__ __forceinline__ void gsync(int id, int nb) {
    __syncthreads();
    if (threadIdx.x == 0) {
        __threadfence();
        atomicAdd(&g_barcnt[id], 1u);
        while (*(volatile unsigned*)&g_barcnt[id] < (unsigned)nb) { __nanosleep(64); }
    }
    __syncthreads();
}

__device__ __forceinline__ float blockSum256(float v, float* buf) {
    int tid = threadIdx.x;
    buf[tid] = v;
    __syncthreads();
    for (int s = 128; s > 0; s >>= 1) {
        if (tid < s) buf[tid] += buf[tid + s];
        __syncthreads();
    }
    float r = buf[0];
    __syncthreads();
    return r;
}

__global__ void __launch_bounds__(256, 2)
k_mega(const float* __restrict__ x, const float* __restrict__ w_dq,
       const float* __restrict__ w_uq_qr, const float* __restrict__ w_uk,
       const float* __restrict__ w_dkv, const float* __restrict__ gamma_cq,
       const float* __restrict__ gamma_ckv, const float* __restrict__ sinp,
       const float* __restrict__ cosp, const int* __restrict__ cidx,
       const float* __restrict__ kvc, const float* __restrict__ krc,
       const int* __restrict__ bt, const int* __restrict__ act_seqs,
       const float* __restrict__ w_idx_qb, const float* __restrict__ w_idxk,
       const float* __restrict__ w_idx_proj, const float* __restrict__ in_g,
       const float* __restrict__ in_b, const float* __restrict__ ikc,
       float* __restrict__ out, int nb)
{
    __shared__ __align__(16) char sm_raw[SMSZ];
    int tid = threadIdx.x;
    int bx = blockIdx.x;

    // ===== P0: stage1 partials, ALL 16 batches per block, weights read once =====
    {
        float* s_x = (float*)sm_raw;   // 16*128 floats = 8KB
        for (int u = bx; u < 6 * NZ1; u += nb) {
            int cx = u % 6, z = u / 6;
            int i0 = z * 128;
            for (int idx = tid; idx < 16 * 128; idx += 256) {
                int bb = idx >> 7, ii = idx & 127;
                s_x[idx] = x[bb * HDIM + i0 + ii];
            }
            __syncthreads();
            int col = cx * 256 + tid;
            if (col < T1DIM) {
                const float* W; int stride, c;
                if (col < QL)                 { W = w_dq;   stride = QL;       c = col; }
                else if (col < QL + KVL + DR) { W = w_dkv;  stride = KVL + DR; c = col - QL; }
                else                          { W = w_idxk; stride = IDXD;     c = col - (QL + KVL + DR); }
                const float* wp = W + (size_t)i0 * stride + c;
                float acc[16];
                #pragma unroll
                for (int b = 0; b < 16; b++) acc[b] = 0.f;
                #pragma unroll 4
                for (int i = 0; i < 128; i++) {
                    float w = wp[(size_t)i * stride];
                    #pragma unroll
                    for (int b = 0; b < 16; b++) acc[b] += s_x[b * 128 + i] * w;
                }
                #pragma unroll
                for (int b = 0; b < 16; b++) g_t1p[z][b][col] = acc[b];
            }
            __syncthreads();
        }
    }
    gsync(0, nb);

    // ===== P1: norms + rope(kr) =====
    {
        float* s_t  = (float*)sm_raw;
        float* sred = (float*)(sm_raw + T1DIM * 4 + 64);
        for (int u = bx; u < BS; u += nb) {
            int b = u;
            for (int i = tid; i < T1DIM; i += 256) {
                float a = 0.f;
                #pragma unroll
                for (int z = 0; z < NZ1; z++) a += g_t1p[z][b][i];
                s_t[i] = a;
            }
            __syncthreads();
            float ss = 0.f;
            for (int i = tid; i < QL; i += 256) ss += s_t[i] * s_t[i];
            ss = blockSum256(ss, sred);
            float r = rsqrtf(ss / (float)QL + 1e-6f);
            for (int i = tid; i < QL; i += 256) g_cq[b][i] = s_t[i] * r * gamma_cq[i];
            float s2 = 0.f;
            for (int i = tid; i < KVL; i += 256) { float v = s_t[QL + i]; s2 += v * v; }
            s2 = blockSum256(s2, sred);
            float r2 = rsqrtf(s2 / (float)KVL + 1e-6f);
            for (int i = tid; i < KVL; i += 256) g_ckv[b][i] = s_t[QL + i] * r2 * gamma_ckv[i];
            if (tid < DR) {
                int d = tid;
                float v = s_t[QL + KVL + d];
                float rot = (d < 32) ? -s_t[QL + KVL + d + 32] : s_t[QL + KVL + d - 32];
                g_kr[b][d] = v * cosp[b * DR + d] + rot * sinp[b * DR + d];
            }
            float sm = 0.f;
            for (int i = tid; i < IDXD; i += 256) sm += s_t[QL + KVL + DR + i];
            sm = blockSum256(sm, sred);
            float mean = sm / (float)IDXD;
            float sv = 0.f;
            for (int i = tid; i < IDXD; i += 256) { float c = s_t[QL + KVL + DR + i] - mean; sv += c * c; }
            sv = blockSum256(sv, sred);
            float rv = rsqrtf(sv / (float)IDXD + 1e-6f);
            for (int i = tid; i < IDXD; i += 256) {
                float c = s_t[QL + KVL + DR + i] - mean;
                g_ki[b][i] = c * rv * in_g[i] + in_b[i];
            }
            __syncthreads();
        }
    }
    gsync(1, nb);

    // ===== P2: stage2 partials, all batches per block, weights read once =====
    {
        float* s_cq = (float*)sm_raw;   // 16*48 floats
        for (int u = bx; u < 17 * NZ2; u += nb) {
            int cx = u % 17, z = u / 17;
            int i0 = z * 48;
            for (int idx = tid; idx < 16 * 48; idx += 256) {
                int bb = idx / 48, ii = idx % 48;
                s_cq[idx] = g_cq[bb][i0 + ii];
            }
            __syncthreads();
            int col = cx * 256 + tid;
            if (col < T2DIM) {
                const float* W; int stride, c;
                if (col < 3072)      { W = w_uq_qr;    stride = 3072; c = col; }
                else if (col < 4096) { W = w_idx_qb;   stride = 1024; c = col - 3072; }
                else                 { W = w_idx_proj; stride = 8;    c = col - 4096; }
                const float* wp = W + (size_t)i0 * stride + c;
                float acc[16];
                #pragma unroll
                for (int b = 0; b < 16; b++) acc[b] = 0.f;
                #pragma unroll 4
                for (int i = 0; i < 48; i++) {
                    float w = wp[(size_t)i * stride];
                    #pragma unroll
                    for (int b = 0; b < 16; b++) acc[b] += s_cq[b * 48 + i] * w;
                }
                #pragma unroll
                for (int b = 0; b < 16; b++) g_t2p[z][b][col] = acc[b];
            }
            __syncthreads();
        }
    }
    gsync(2, nb);

    // ===== P2b: reduce stage2 partials into g_q / g_qi / g_hw =====
    {
        int total = BS * T2DIM;
        for (int idx = bx * 256 + tid; idx < total; idx += nb * 256) {
            int b = idx / T2DIM, col = idx % T2DIM;
            float a = 0.f;
            #pragma unroll
            for (int z = 0; z < NZ2; z++) a += g_t2p[z][b][col];
            if (col < 3072)      g_q[b][col] = a;
            else if (col < 4096) g_qi[b][col - 3072] = a;
            else                 g_hw[b][col - 4096] = a;
        }
    }
    gsync(3, nb);

    // ===== P3: qprep (32 units, w_uk read once) + iscore (512 units) =====
    {
        for (int u = bx; u < 32 + 512; u += nb) {
            if (u < 32) {
                int h = u & 15, cc = u >> 4;
                float* s_qn = (float*)sm_raw;   // 16*128 floats
                for (int idx = tid; idx < 2048; idx += 256) {
                    int bb = idx >> 7, d = idx & 127;
                    s_qn[idx] = g_q[bb][h * 192 + d];
                }
                if (cc == 0) {
                    for (int idx = tid; idx < 1024; idx += 256) {
                        int bb = idx >> 6, d = idx & 63;
                        float v = g_q[bb][h * 192 + DN + d];
                        float rot = (d < 32) ? -g_q[bb][h * 192 + DN + d + 32] : g_q[bb][h * 192 + DN + d - 32];
                        g_qpe[bb][h][d] = v * cosp[bb * DR + d] + rot * sinp[bb * DR + d];
                    }
                }
                __syncthreads();
                int c = cc * 256 + tid;
                const float* wk = w_uk + (size_t)h * DN * KVL + c;
                float acc[16];
                #pragma unroll
                for (int b = 0; b < 16; b++) acc[b] = 0.f;
                #pragma unroll 4
                for (int d = 0; d < DN; d++) {
                    float w = wk[(size_t)d * KVL];
                    #pragma unroll
                    for (int b = 0; b < 16; b++) acc[b] += s_qn[b * 128 + d] * w;
                }
                #pragma unroll
                for (int b = 0; b < 16; b++) g_qlat[b][h][c] = acc[b];
                __syncthreads();
            } else {
                int u2 = u - 32;
                int chunk = u2 & 31, b = u2 >> 5;
                float* s_qi = (float*)sm_raw;
                float* s_hw = (float*)(sm_raw + 4096);
                for (int i = tid; i < NIH * IDXD; i += 256) s_qi[i] = g_qi[b][i];
                if (tid < NIH) s_hw[tid] = g_hw[b][tid];
                __syncthreads();
                int warp = tid >> 5, lane = tid & 31;
                int act = act_seqs[b];
                int ci = cidx[b];
                for (int r = warp; r < 128; r += 8) {
                    int n = chunk * 128 + r;
                    if (n >= act) { if (lane == 0) g_isc[b][n] = -1e9f; continue; }
                    int blk = bt[b * BPS + (n >> 7)];
                    long flat = (long)blk * BLKSZ + (n & 127);
                    const float* kr = (flat == (long)ci) ? g_ki[b] : ikc + flat * IDXD;
                    float4 kv = *(const float4*)(kr + lane * 4);
                    float acc[NIH];
                    #pragma unroll
                    for (int h = 0; h < NIH; h++) {
                        float4 q = *(const float4*)&s_qi[h * IDXD + lane * 4];
                        acc[h] = kv.x * q.x + kv.y * q.y + kv.z * q.z + kv.w * q.w;
                    }
                    #pragma unroll
                    for (int off = 16; off; off >>= 1) {
                        #pragma unroll
                        for (int h = 0; h < NIH; h++)
                            acc[h] += __shfl_xor_sync(0xffffffffu, acc[h], off);
                    }
                    if (lane == 0) {
                        float s = 0.f;
                        #pragma unroll
                        for (int h = 0; h < NIH; h++) s += s_hw[h] * fmaxf(acc[h], 0.f);
                        g_isc[b][n] = s * IDX_SCALE;
                    }
                }
                __syncthreads();
            }
        }
    }
    gsync(4, nb);

    // ===== P4: top-k radix threshold select =====
    {
        unsigned* s_key  = (unsigned*)sm_raw;
        unsigned* s_hist = (unsigned*)(sm_raw + 16384);
        unsigned* s_scan = (unsigned*)(sm_raw + 17408);
        unsigned* s_bm   = (unsigned*)(sm_raw + 18432);
        unsigned* s_cnt  = (unsigned*)(sm_raw + 18944);
        unsigned* s_pref = (unsigned*)(sm_raw + 18948);
        int*      s_rem  = (int*)(sm_raw + 18952);
        int*      s_Bw   = (int*)(sm_raw + 18956);
        int*      s_need = (int*)(sm_raw + 18960);
        for (int u = bx; u < BS; u += nb) {
            int b = u;
            int act = act_seqs[b];
            for (int i = tid; i < MAXKV; i += 256) {
                float v = (i < act) ? g_isc[b][i] : -1e9f;
                unsigned uu = __float_as_uint(v);
                uu = (uu & 0x80000000u) ? ~uu : (uu | 0x80000000u);
                s_key[i] = uu;
            }
            if (tid == 0) { *s_cnt = 0; *s_rem = TOPK; *s_pref = 0; }
            __syncthreads();
            for (int level = 0; level < 4; level++) {
                int shift = 24 - level * 8;
                s_hist[tid] = 0;
                __syncthreads();
                unsigned pref = *s_pref;
                for (int i = tid; i < MAXKV; i += 256) {
                    unsigned uu = s_key[i];
                    if (level == 0 || (uu >> (shift + 8)) == pref)
                        atomicAdd(&s_hist[(uu >> shift) & 255u], 1u);
                }
                __syncthreads();
                s_scan[tid] = s_hist[tid];
                __syncthreads();
                #pragma unroll
                for (int off = 1; off < 256; off <<= 1) {
                    unsigned t = (tid + off < 256) ? s_scan[tid + off] : 0u;
                    __syncthreads();
                    s_scan[tid] += t;
                    __syncthreads();
                }
                int rem = *s_rem;
                unsigned cumGT = s_scan[tid] - s_hist[tid];
                if ((int)cumGT < rem && (int)s_scan[tid] >= rem) {
                    *s_pref = (pref << 8) | (unsigned)tid;
                    *s_rem = rem - (int)cumGT;
                }
                __syncthreads();
            }
            unsigned K = *s_pref;
            for (int i = tid; i < MAXKV; i += 256) {
                if (s_key[i] > K) {
                    unsigned pos = atomicAdd(s_cnt, 1u);
                    g_sel[b][pos] = i;
                    g_selval[b][pos] = (i < act) ? g_isc[b][i] : -1e9f;
                }
            }
            for (int w = tid; w < MAXKV / 32; w += 256) s_bm[w] = 0;
            __syncthreads();
            for (int i = tid; i < MAXKV; i += 256)
                if (s_key[i] == K) atomicOr(&s_bm[i >> 5], 1u << (i & 31));
            __syncthreads();
            if (tid == 0) {
                int need = *s_rem;
                int w = 0;
                for (; w < MAXKV / 32; w++) {
                    int pc = __popc(s_bm[w]);
                    if (pc >= need) break;
                    need -= pc;
                }
                *s_Bw = w; *s_need = need;
            }
            __syncthreads();
            int Bw = *s_Bw, need = *s_need;
            for (int i = tid; i < MAXKV; i += 256) {
                if (s_key[i] == K) {
                    int w = i >> 5, bit = i & 31;
                    bool take = (w < Bw) ||
                                (w == Bw && (int)__popc(s_bm[w] & ((1u << bit) - 1u)) < need);
                    if (take) {
                        unsigned pos = atomicAdd(s_cnt, 1u);
                        g_sel[b][pos] = i;
                        g_selval[b][pos] = (i < act) ? g_isc[b][i] : -1e9f;
                    }
                }
            }
            __syncthreads();
        }
    }
    gsync(5, nb);

    // ===== P5: attention partials =====
    {
        float* s_qlat = (float*)sm_raw;
        float* s_qpe  = (float*)(sm_raw + 32768);
        float* s_sc   = (float*)(sm_raw + 36864);
        const float** s_ckvp = (const float**)(sm_raw + 40960);
        const float** s_krp  = (const float**)(sm_raw + 41472);
        int* s_vld = (int*)(sm_raw + 41984);
        for (int u = bx; u < NSPLIT * BS; u += nb) {
            int s = u & 15, b = u >> 4;
            const float* qlb = &g_qlat[b][0][0];
            for (int i = tid; i < NH * KVL; i += 256) s_qlat[i] = qlb[i];
            const float* qpb = &g_qpe[b][0][0];
            for (int i = tid; i < NH * DR; i += 256) s_qpe[i] = qpb[i];
            if (tid < SPLITROWS) {
                int j = tid;
                int n = g_sel[b][s * SPLITROWS + j];
                float v = g_selval[b][s * SPLITROWS + j];
                bool valid = v > -1e8f;
                const float* cp; const float* kp;
                if (!valid) { cp = g_ckv[b]; kp = g_kr[b]; }
                else {
                    int blk = bt[b * BPS + (n >> 7)];
                    long flat = (long)blk * BLKSZ + (n & 127);
                    if (flat == (long)cidx[b]) { cp = g_ckv[b]; kp = g_kr[b]; }
                    else { cp = kvc + flat * KVL; kp = krc + flat * DR; }
                }
                s_ckvp[j] = cp; s_krp[j] = kp; s_vld[j] = valid ? 1 : 0;
            }
            __syncthreads();
            int warp = tid >> 5, lane = tid & 31;
            for (int j = warp; j < SPLITROWS; j += 8) {
                const float* ckv = s_ckvp[j];
                const float* krp = s_krp[j];
                float acc[NH];
                #pragma unroll
                for (int h = 0; h < NH; h++) acc[h] = 0.f;
                #pragma unroll
                for (int q = 0; q < 4; q++) {
                    float4 v = *(const float4*)(ckv + 4 * (lane + 32 * q));
                    #pragma unroll
                    for (int h = 0; h < NH; h++) {
                        float4 ql = *(const float4*)&s_qlat[h * KVL + 4 * (lane + 32 * q)];
                        acc[h] += v.x * ql.x + v.y * ql.y + v.z * ql.z + v.w * ql.w;
                    }
                }
                float2 kv2 = *(const float2*)(krp + 2 * lane);
                #pragma unroll
                for (int h = 0; h < NH; h++) {
                    float2 qp = *(const float2*)&s_qpe[h * DR + 2 * lane];
                    acc[h] += kv2.x * qp.x + kv2.y * qp.y;
                }
                #pragma unroll
                for (int off = 16; off; off >>= 1) {
                    #pragma unroll
                    for (int h = 0; h < NH; h++)
                        acc[h] += __shfl_xor_sync(0xffffffffu, acc[h], off);
                }
                if (lane == 0) {
                    bool valid = s_vld[j] != 0;
                    #pragma unroll
                    for (int h = 0; h < NH; h++)
                        s_sc[j * NH + h] = valid ? acc[h] * ATT_SCALE : -1e9f;
                }
            }
            __syncthreads();
            for (int h = warp; h < NH; h += 8) {
                float v0 = s_sc[(lane +  0) * NH + h];
                float v1 = s_sc[(lane + 32) * NH + h];
                float m = fmaxf(v0, v1);
                #pragma unroll
                for (int off = 16; off; off >>= 1) m = fmaxf(m, __shfl_xor_sync(0xffffffffu, m, off));
                float e0 = __expf(v0 - m), e1 = __expf(v1 - m);
                s_sc[(lane +  0) * NH + h] = e0;
                s_sc[(lane + 32) * NH + h] = e1;
                float l = e0 + e1;
                #pragma unroll
                for (int off = 16; off; off >>= 1) l += __shfl_xor_sync(0xffffffffu, l, off);
                if (lane == 0) { g_m[b][s][h] = m; g_l[b][s][h] = l; }
            }
            __syncthreads();
            #pragma unroll
            for (int half = 0; half < 2; half++) {
                int c = half * 256 + tid;
                float acc[NH];
                #pragma unroll
                for (int h = 0; h < NH; h++) acc[h] = 0.f;
                #pragma unroll 4
                for (int j = 0; j < SPLITROWS; j++) {
                    float v = s_ckvp[j][c];
                    float4 p0 = *(const float4*)&s_sc[j * NH + 0];
                    float4 p1 = *(const float4*)&s_sc[j * NH + 4];
                    float4 p2 = *(const float4*)&s_sc[j * NH + 8];
                    float4 p3 = *(const float4*)&s_sc[j * NH + 12];
                    acc[0]  += p0.x * v; acc[1]  += p0.y * v; acc[2]  += p0.z * v; acc[3]  += p0.w * v;
                    acc[4]  += p1.x * v; acc[5]  += p1.y * v; acc[6]  += p1.z * v; acc[7]  += p1.w * v;
                    acc[8]  += p2.x * v; acc[9]  += p2.y * v; acc[10] += p2.z * v; acc[11] += p2.w * v;
                    acc[12] += p3.x * v; acc[13] += p3.y * v; acc[14] += p3.z * v; acc[15] += p3.w * v;
                }
                #pragma unroll
                for (int h = 0; h < NH; h++) g_op[b][s][h][c] = acc[h];
            }
            __syncthreads();
        }
    }
    gsync(6, nb);

    // ===== P6: combine + output projection =====
    {
        float* s_olat = (float*)sm_raw;
        float* s_w    = (float*)(sm_raw + 2048);
        float* s_invl = (float*)(sm_raw + 2112);
        for (int u = bx; u < NH * BS; u += nb) {
            int h = u & 15, b = u >> 4;
            if (tid == 0) {
                float M = -1e30f;
                for (int s = 0; s < NSPLIT; s++) M = fmaxf(M, g_m[b][s][h]);
                float L = 0.f;
                for (int s = 0; s < NSPLIT; s++) {
                    float w = __expf(g_m[b][s][h] - M);
                    s_w[s] = w;
                    L += g_l[b][s][h] * w;
                }
                *s_invl = 1.f / L;
            }
            __syncthreads();
            for (int c = tid; c < KVL; c += 256) {
                float a = 0.f;
                #pragma unroll
                for (int s = 0; s < NSPLIT; s++) a += g_op[b][s][h][c] * s_w[s];
                s_olat[c] = a * (*s_invl);
            }
            __syncthreads();
            if (tid < DN) {
                int d = tid;
                const float* wk = w_uk + ((size_t)(h * DN + d)) * KVL;
                float a = 0.f;
                #pragma unroll 8
                for (int c = 0; c < KVL; c += 4) {
                    float4 o4 = *(const float4*)&s_olat[c];
                    float4 w4 = *(const float4*)&wk[c];
                    a += o4.x * w4.x + o4.y * w4.y + o4.z * w4.z + o4.w * w4.w;
                }
                out[b * (NH * DN) + h * DN + d] = a;
            }
            __syncthreads();
        }
    }

    // reset barrier state for next graph replay (ack ensures no block still spins)
    __syncthreads();
    if (tid == 0) {
        __threadfence();
        unsigned a = atomicAdd(&g_ack, 1u) + 1;
        if (a == (unsigned)nb) {
            #pragma unroll
            for (int i = 0; i < 16; i++) g_barcnt[i] = 0;
            g_ack = 0;
            __threadfence();
        }
    }
}

// ---------------- launch ----------------
extern "C" void kernel_launch(void* const* d_in, const int* in_sizes, int n_in,
                              void* d_out, int out_size) {
    const float* x            = (const float*)d_in[0];
    const float* w_dq         = (const float*)d_in[1];
    const float* w_uq_qr      = (const float*)d_in[2];
    const float* w_uk         = (const float*)d_in[3];
    const float* w_dkv_kr     = (const float*)d_in[4];
    const float* gamma_cq     = (const float*)d_in[5];
    const float* gamma_ckv    = (const float*)d_in[6];
    const float* sinp         = (const float*)d_in[7];
    const float* cosp         = (const float*)d_in[8];
    const int*   cache_index  = (const int*)d_in[9];
    const float* kv_cache     = (const float*)d_in[10];
    const float* kr_cache     = (const float*)d_in[11];
    const int*   block_table  = (const int*)d_in[12];
    const int*   act_seqs     = (const int*)d_in[13];
    const float* w_idx_qb     = (const float*)d_in[14];
    const float* w_idx_k      = (const float*)d_in[15];
    const float* w_idx_proj   = (const float*)d_in[16];
    const float* in_gamma_k   = (const float*)d_in[17];
    const float* in_beta_k    = (const float*)d_in[18];
    const float* index_k_cache= (const float*)d_in[19];
    float* out = (float*)d_out;

    int sms = 148, bpm = 0;
    cudaDeviceGetAttribute(&sms, cudaDevAttrMultiProcessorCount, 0);
    cudaOccupancyMaxActiveBlocksPerMultiprocessor(&bpm, k_mega, 256, 0);
    if (bpm < 1) bpm = 1;
    int nb = bpm * sms;
    if (nb > NBMAX) nb = NBMAX;

    k_mega<<<nb, 256>>>(x, w_dq, w_uq_qr, w_uk, w_dkv_kr, gamma_cq, gamma_ckv,
                        sinp, cosp, cache_index, kv_cache, kr_cache, block_table,
                        act_seqs, w_idx_qb, w_idx_k, w_idx_proj, in_gamma_k,
                        in_beta_k, index_k_cache, out, nb);
}

// round 7
// speedup vs baseline: 1.8811x; 1.0742x over previous
#include <cuda_runtime.h>
#include <cuda_bf16.h>
#include <math.h>

#define BS 16
#define HDIM 2048
#define QL 768
#define KVL 512
#define DR 64
#define DN 128
#define NH 16
#define NIH 8
#define IDXD 128
#define BLKSZ 128
#define BPS 32
#define MAXKV 4096
#define TOPK 1024
#define NSPLIT 16
#define SPLITROWS 64

#define NZ1 32          /* stage1 K-slices of 64 */
#define NZ2 12          /* stage2 K-slices of 64 */
#define T1DIM 1472
#define T2DIM 4104

#define ATT_SCALE 0.07216878364870323f
#define IDX_SCALE 0.08838834764831845f

#define NBMAX 448
#define SMSZ 42240

// ---------------- scratch ----------------
__device__ float g_t1p[NZ1][BS][T1DIM];
__device__ float g_t2p[NZ2][BS][T2DIM];
__device__ float g_cq[BS][QL];
__device__ float g_ckv[BS][KVL];
__device__ float g_kr[BS][DR];
__device__ float g_ki[BS][IDXD];
__device__ float g_q[BS][NH * 192];
__device__ float g_qi[BS][NIH * IDXD];
__device__ float g_hw[BS][NIH];
__device__ float g_qpe[BS][NH][DR];
__device__ float g_qlat[BS][NH][KVL];
__device__ float g_isc[BS][MAXKV];
__device__ int   g_sel[BS][TOPK];
__device__ float g_selval[BS][TOPK];
__device__ float g_m[BS][NSPLIT][NH];
__device__ float g_l[BS][NSPLIT][NH];
__device__ float g_op[BS][NSPLIT][NH][KVL];

// grid barrier state (reset in-kernel before exit)
__device__ unsigned g_barcnt[16];
__device__ unsigned g_ack;

__device__ __forceinline__ void gsync(int id, int nb) {
    __syncthreads();
    if (threadIdx.x == 0) {
        __threadfence();
        atomicAdd(&g_barcnt[id], 1u);
        while (*(volatile unsigned*)&g_barcnt[id] < (unsigned)nb) { __nanosleep(64); }
    }
    __syncthreads();
}

__device__ __forceinline__ float blockSum256(float v, float* buf) {
    int tid = threadIdx.x;
    buf[tid] = v;
    __syncthreads();
    for (int s = 128; s > 0; s >>= 1) {
        if (tid < s) buf[tid] += buf[tid + s];
        __syncthreads();
    }
    float r = buf[0];
    __syncthreads();
    return r;
}

__global__ void __launch_bounds__(256, 3)
k_mega(const float* __restrict__ x, const float* __restrict__ w_dq,
       const float* __restrict__ w_uq_qr, const float* __restrict__ w_uk,
       const float* __restrict__ w_dkv, const float* __restrict__ gamma_cq,
       const float* __restrict__ gamma_ckv, const float* __restrict__ sinp,
       const float* __restrict__ cosp, const int* __restrict__ cidx,
       const float* __restrict__ kvc, const float* __restrict__ krc,
       const int* __restrict__ bt, const int* __restrict__ act_seqs,
       const float* __restrict__ w_idx_qb, const float* __restrict__ w_idxk,
       const float* __restrict__ w_idx_proj, const float* __restrict__ in_g,
       const float* __restrict__ in_b, const float* __restrict__ ikc,
       float* __restrict__ out, int nb)
{
    __shared__ __align__(16) char sm_raw[SMSZ];
    int tid = threadIdx.x;
    int bx = blockIdx.x;

    // ===== P0: stage1 partials, 8 batches/unit, 64-deep K slices (384 units) =====
    {
        float* s_x = (float*)sm_raw;   // 8*64 floats
        for (int u = bx; u < 6 * 2 * NZ1; u += nb) {
            int cx = u % 6, bg = (u / 6) & 1, z = u / 12;
            int i0 = z * 64, b0 = bg * 8;
            for (int idx = tid; idx < 8 * 64; idx += 256) {
                int bb = idx >> 6, ii = idx & 63;
                s_x[idx] = x[(b0 + bb) * HDIM + i0 + ii];
            }
            __syncthreads();
            int col = cx * 256 + tid;
            if (col < T1DIM) {
                const float* W; int stride, c;
                if (col < QL)                 { W = w_dq;   stride = QL;       c = col; }
                else if (col < QL + KVL + DR) { W = w_dkv;  stride = KVL + DR; c = col - QL; }
                else                          { W = w_idxk; stride = IDXD;     c = col - (QL + KVL + DR); }
                const float* wp = W + (size_t)i0 * stride + c;
                float acc[8];
                #pragma unroll
                for (int b = 0; b < 8; b++) acc[b] = 0.f;
                #pragma unroll 8
                for (int i = 0; i < 64; i++) {
                    float w = wp[(size_t)i * stride];
                    #pragma unroll
                    for (int b = 0; b < 8; b++) acc[b] += s_x[b * 64 + i] * w;
                }
                #pragma unroll
                for (int b = 0; b < 8; b++) g_t1p[z][b0 + b][col] = acc[b];
            }
            __syncthreads();
        }
    }
    gsync(0, nb);

    // ===== P1: norms + rope(kr) =====
    {
        float* s_t  = (float*)sm_raw;
        float* sred = (float*)(sm_raw + T1DIM * 4 + 64);
        for (int u = bx; u < BS; u += nb) {
            int b = u;
            for (int i = tid; i < T1DIM; i += 256) {
                float a = 0.f;
                #pragma unroll
                for (int z = 0; z < NZ1; z++) a += g_t1p[z][b][i];
                s_t[i] = a;
            }
            __syncthreads();
            float ss = 0.f;
            for (int i = tid; i < QL; i += 256) ss += s_t[i] * s_t[i];
            ss = blockSum256(ss, sred);
            float r = rsqrtf(ss / (float)QL + 1e-6f);
            for (int i = tid; i < QL; i += 256) g_cq[b][i] = s_t[i] * r * gamma_cq[i];
            float s2 = 0.f;
            for (int i = tid; i < KVL; i += 256) { float v = s_t[QL + i]; s2 += v * v; }
            s2 = blockSum256(s2, sred);
            float r2 = rsqrtf(s2 / (float)KVL + 1e-6f);
            for (int i = tid; i < KVL; i += 256) g_ckv[b][i] = s_t[QL + i] * r2 * gamma_ckv[i];
            if (tid < DR) {
                int d = tid;
                float v = s_t[QL + KVL + d];
                float rot = (d < 32) ? -s_t[QL + KVL + d + 32] : s_t[QL + KVL + d - 32];
                g_kr[b][d] = v * cosp[b * DR + d] + rot * sinp[b * DR + d];
            }
            float sm = 0.f;
            for (int i = tid; i < IDXD; i += 256) sm += s_t[QL + KVL + DR + i];
            sm = blockSum256(sm, sred);
            float mean = sm / (float)IDXD;
            float sv = 0.f;
            for (int i = tid; i < IDXD; i += 256) { float c = s_t[QL + KVL + DR + i] - mean; sv += c * c; }
            sv = blockSum256(sv, sred);
            float rv = rsqrtf(sv / (float)IDXD + 1e-6f);
            for (int i = tid; i < IDXD; i += 256) {
                float c = s_t[QL + KVL + DR + i] - mean;
                g_ki[b][i] = c * rv * in_g[i] + in_b[i];
            }
            __syncthreads();
        }
    }
    gsync(1, nb);

    // ===== P2: stage2 partials, 8 batches/unit, 64-deep K slices (408 units) =====
    {
        float* s_cq = (float*)sm_raw;   // 8*64 floats
        for (int u = bx; u < 17 * 2 * NZ2; u += nb) {
            int cx = u % 17, bg = (u / 17) & 1, z = u / 34;
            int i0 = z * 64, b0 = bg * 8;
            for (int idx = tid; idx < 8 * 64; idx += 256) {
                int bb = idx >> 6, ii = idx & 63;
                s_cq[idx] = g_cq[b0 + bb][i0 + ii];
            }
            __syncthreads();
            int col = cx * 256 + tid;
            if (col < T2DIM) {
                const float* W; int stride, c;
                if (col < 3072)      { W = w_uq_qr;    stride = 3072; c = col; }
                else if (col < 4096) { W = w_idx_qb;   stride = 1024; c = col - 3072; }
                else                 { W = w_idx_proj; stride = 8;    c = col - 4096; }
                const float* wp = W + (size_t)i0 * stride + c;
                float acc[8];
                #pragma unroll
                for (int b = 0; b < 8; b++) acc[b] = 0.f;
                #pragma unroll 8
                for (int i = 0; i < 64; i++) {
                    float w = wp[(size_t)i * stride];
                    #pragma unroll
                    for (int b = 0; b < 8; b++) acc[b] += s_cq[b * 64 + i] * w;
                }
                #pragma unroll
                for (int b = 0; b < 8; b++) g_t2p[z][b0 + b][col] = acc[b];
            }
            __syncthreads();
        }
    }
    gsync(2, nb);

    // ===== P2b: reduce stage2 partials into g_q / g_qi / g_hw =====
    {
        int total = BS * T2DIM;
        for (int idx = bx * 256 + tid; idx < total; idx += nb * 256) {
            int b = idx / T2DIM, col = idx % T2DIM;
            float a = 0.f;
            #pragma unroll
            for (int z = 0; z < NZ2; z++) a += g_t2p[z][b][col];
            if (col < 3072)      g_q[b][col] = a;
            else if (col < 4096) g_qi[b][col - 3072] = a;
            else                 g_hw[b][col - 4096] = a;
        }
    }
    gsync(3, nb);

    // ===== P3: iscore (512 units) =====
    {
        float* s_qi = (float*)sm_raw;
        float* s_hw = (float*)(sm_raw + 4096);
        for (int u = bx; u < 512; u += nb) {
            int chunk = u & 31, b = u >> 5;
            for (int i = tid; i < NIH * IDXD; i += 256) s_qi[i] = g_qi[b][i];
            if (tid < NIH) s_hw[tid] = g_hw[b][tid];
            __syncthreads();
            int warp = tid >> 5, lane = tid & 31;
            int act = act_seqs[b];
            int ci = cidx[b];
            for (int r = warp; r < 128; r += 8) {
                int n = chunk * 128 + r;
                if (n >= act) { if (lane == 0) g_isc[b][n] = -1e9f; continue; }
                int blk = bt[b * BPS + (n >> 7)];
                long flat = (long)blk * BLKSZ + (n & 127);
                const float* kr = (flat == (long)ci) ? g_ki[b] : ikc + flat * IDXD;
                float4 kv = *(const float4*)(kr + lane * 4);
                float acc[NIH];
                #pragma unroll
                for (int h = 0; h < NIH; h++) {
                    float4 q = *(const float4*)&s_qi[h * IDXD + lane * 4];
                    acc[h] = kv.x * q.x + kv.y * q.y + kv.z * q.z + kv.w * q.w;
                }
                #pragma unroll
                for (int off = 16; off; off >>= 1) {
                    #pragma unroll
                    for (int h = 0; h < NIH; h++)
                        acc[h] += __shfl_xor_sync(0xffffffffu, acc[h], off);
                }
                if (lane == 0) {
                    float s = 0.f;
                    #pragma unroll
                    for (int h = 0; h < NIH; h++) s += s_hw[h] * fmaxf(acc[h], 0.f);
                    g_isc[b][n] = s * IDX_SCALE;
                }
            }
            __syncthreads();
        }
    }
    gsync(4, nb);

    // ===== P4: top-k (16 units) + qprep (64 units) overlapped =====
    {
        for (int u = bx; u < 16 + 64; u += nb) {
            if (u < 16) {
                // ---- top-k radix threshold select ----
                unsigned* s_key  = (unsigned*)sm_raw;
                unsigned* s_hist = (unsigned*)(sm_raw + 16384);
                unsigned* s_scan = (unsigned*)(sm_raw + 17408);
                unsigned* s_bm   = (unsigned*)(sm_raw + 18432);
                unsigned* s_cnt  = (unsigned*)(sm_raw + 18944);
                unsigned* s_pref = (unsigned*)(sm_raw + 18948);
                int*      s_rem  = (int*)(sm_raw + 18952);
                int*      s_Bw   = (int*)(sm_raw + 18956);
                int*      s_need = (int*)(sm_raw + 18960);
                int b = u;
                int act = act_seqs[b];
                for (int i = tid; i < MAXKV; i += 256) {
                    float v = (i < act) ? g_isc[b][i] : -1e9f;
                    unsigned uu = __float_as_uint(v);
                    uu = (uu & 0x80000000u) ? ~uu : (uu | 0x80000000u);
                    s_key[i] = uu;
                }
                if (tid == 0) { *s_cnt = 0; *s_rem = TOPK; *s_pref = 0; }
                __syncthreads();
                for (int level = 0; level < 4; level++) {
                    int shift = 24 - level * 8;
                    s_hist[tid] = 0;
                    __syncthreads();
                    unsigned pref = *s_pref;
                    for (int i = tid; i < MAXKV; i += 256) {
                        unsigned uu = s_key[i];
                        if (level == 0 || (uu >> (shift + 8)) == pref)
                            atomicAdd(&s_hist[(uu >> shift) & 255u], 1u);
                    }
                    __syncthreads();
                    s_scan[tid] = s_hist[tid];
                    __syncthreads();
                    #pragma unroll
                    for (int off = 1; off < 256; off <<= 1) {
                        unsigned t = (tid + off < 256) ? s_scan[tid + off] : 0u;
                        __syncthreads();
                        s_scan[tid] += t;
                        __syncthreads();
                    }
                    int rem = *s_rem;
                    unsigned cumGT = s_scan[tid] - s_hist[tid];
                    if ((int)cumGT < rem && (int)s_scan[tid] >= rem) {
                        *s_pref = (pref << 8) | (unsigned)tid;
                        *s_rem = rem - (int)cumGT;
                    }
                    __syncthreads();
                }
                unsigned K = *s_pref;
                for (int i = tid; i < MAXKV; i += 256) {
                    if (s_key[i] > K) {
                        unsigned pos = atomicAdd(s_cnt, 1u);
                        g_sel[b][pos] = i;
                        g_selval[b][pos] = (i < act) ? g_isc[b][i] : -1e9f;
                    }
                }
                for (int w = tid; w < MAXKV / 32; w += 256) s_bm[w] = 0;
                __syncthreads();
                for (int i = tid; i < MAXKV; i += 256)
                    if (s_key[i] == K) atomicOr(&s_bm[i >> 5], 1u << (i & 31));
                __syncthreads();
                if (tid == 0) {
                    int need = *s_rem;
                    int w = 0;
                    for (; w < MAXKV / 32; w++) {
                        int pc = __popc(s_bm[w]);
                        if (pc >= need) break;
                        need -= pc;
                    }
                    *s_Bw = w; *s_need = need;
                }
                __syncthreads();
                int Bw = *s_Bw, need = *s_need;
                for (int i = tid; i < MAXKV; i += 256) {
                    if (s_key[i] == K) {
                        int w = i >> 5, bit = i & 31;
                        bool take = (w < Bw) ||
                                    (w == Bw && (int)__popc(s_bm[w] & ((1u << bit) - 1u)) < need);
                        if (take) {
                            unsigned pos = atomicAdd(s_cnt, 1u);
                            g_sel[b][pos] = i;
                            g_selval[b][pos] = (i < act) ? g_isc[b][i] : -1e9f;
                        }
                    }
                }
                __syncthreads();
            } else {
                // ---- qprep: 8 batches/unit ----
                int u2 = u - 16;
                int h = u2 & 15, r = u2 >> 4;
                int cc = r & 1, bg = r >> 1;
                int b0 = bg * 8;
                float* s_qn = (float*)sm_raw;   // 8*128 floats
                for (int idx = tid; idx < 1024; idx += 256) {
                    int bb = idx >> 7, d = idx & 127;
                    s_qn[idx] = g_q[b0 + bb][h * 192 + d];
                }
                if (cc == 0) {
                    for (int idx = tid; idx < 512; idx += 256) {
                        int bb = idx >> 6, d = idx & 63;
                        int b = b0 + bb;
                        float v = g_q[b][h * 192 + DN + d];
                        float rot = (d < 32) ? -g_q[b][h * 192 + DN + d + 32] : g_q[b][h * 192 + DN + d - 32];
                        g_qpe[b][h][d] = v * cosp[b * DR + d] + rot * sinp[b * DR + d];
                    }
                }
                __syncthreads();
                int c = cc * 256 + tid;
                const float* wk = w_uk + (size_t)h * DN * KVL + c;
                float acc[8];
                #pragma unroll
                for (int b = 0; b < 8; b++) acc[b] = 0.f;
                #pragma unroll 8
                for (int d = 0; d < DN; d++) {
                    float w = wk[(size_t)d * KVL];
                    #pragma unroll
                    for (int b = 0; b < 8; b++) acc[b] += s_qn[b * 128 + d] * w;
                }
                #pragma unroll
                for (int b = 0; b < 8; b++) g_qlat[b0 + b][h][c] = acc[b];
                __syncthreads();
            }
        }
    }
    gsync(5, nb);

    // ===== P5: attention partials (256 units) =====
    {
        float* s_qlat = (float*)sm_raw;
        float* s_qpe  = (float*)(sm_raw + 32768);
        float* s_sc   = (float*)(sm_raw + 36864);
        const float** s_ckvp = (const float**)(sm_raw + 40960);
        const float** s_krp  = (const float**)(sm_raw + 41472);
        int* s_vld = (int*)(sm_raw + 41984);
        for (int u = bx; u < NSPLIT * BS; u += nb) {
            int s = u & 15, b = u >> 4;
            const float* qlb = &g_qlat[b][0][0];
            for (int i = tid; i < NH * KVL; i += 256) s_qlat[i] = qlb[i];
            const float* qpb = &g_qpe[b][0][0];
            for (int i = tid; i < NH * DR; i += 256) s_qpe[i] = qpb[i];
            if (tid < SPLITROWS) {
                int j = tid;
                int n = g_sel[b][s * SPLITROWS + j];
                float v = g_selval[b][s * SPLITROWS + j];
                bool valid = v > -1e8f;
                const float* cp; const float* kp;
                if (!valid) { cp = g_ckv[b]; kp = g_kr[b]; }
                else {
                    int blk = bt[b * BPS + (n >> 7)];
                    long flat = (long)blk * BLKSZ + (n & 127);
                    if (flat == (long)cidx[b]) { cp = g_ckv[b]; kp = g_kr[b]; }
                    else { cp = kvc + flat * KVL; kp = krc + flat * DR; }
                }
                s_ckvp[j] = cp; s_krp[j] = kp; s_vld[j] = valid ? 1 : 0;
            }
            __syncthreads();
            int warp = tid >> 5, lane = tid & 31;
            for (int j = warp; j < SPLITROWS; j += 8) {
                const float* ckv = s_ckvp[j];
                const float* krp = s_krp[j];
                float acc[NH];
                #pragma unroll
                for (int h = 0; h < NH; h++) acc[h] = 0.f;
                #pragma unroll
                for (int q = 0; q < 4; q++) {
                    float4 v = *(const float4*)(ckv + 4 * (lane + 32 * q));
                    #pragma unroll
                    for (int h = 0; h < NH; h++) {
                        float4 ql = *(const float4*)&s_qlat[h * KVL + 4 * (lane + 32 * q)];
                        acc[h] += v.x * ql.x + v.y * ql.y + v.z * ql.z + v.w * ql.w;
                    }
                }
                float2 kv2 = *(const float2*)(krp + 2 * lane);
                #pragma unroll
                for (int h = 0; h < NH; h++) {
                    float2 qp = *(const float2*)&s_qpe[h * DR + 2 * lane];
                    acc[h] += kv2.x * qp.x + kv2.y * qp.y;
                }
                #pragma unroll
                for (int off = 16; off; off >>= 1) {
                    #pragma unroll
                    for (int h = 0; h < NH; h++)
                        acc[h] += __shfl_xor_sync(0xffffffffu, acc[h], off);
                }
                if (lane == 0) {
                    bool valid = s_vld[j] != 0;
                    #pragma unroll
                    for (int h = 0; h < NH; h++)
                        s_sc[j * NH + h] = valid ? acc[h] * ATT_SCALE : -1e9f;
                }
            }
            __syncthreads();
            for (int h = warp; h < NH; h += 8) {
                float v0 = s_sc[(lane +  0) * NH + h];
                float v1 = s_sc[(lane + 32) * NH + h];
                float m = fmaxf(v0, v1);
                #pragma unroll
                for (int off = 16; off; off >>= 1) m = fmaxf(m, __shfl_xor_sync(0xffffffffu, m, off));
                float e0 = __expf(v0 - m), e1 = __expf(v1 - m);
                s_sc[(lane +  0) * NH + h] = e0;
                s_sc[(lane + 32) * NH + h] = e1;
                float l = e0 + e1;
                #pragma unroll
                for (int off = 16; off; off >>= 1) l += __shfl_xor_sync(0xffffffffu, l, off);
                if (lane == 0) { g_m[b][s][h] = m; g_l[b][s][h] = l; }
            }
            __syncthreads();
            #pragma unroll
            for (int half = 0; half < 2; half++) {
                int c = half * 256 + tid;
                float acc[NH];
                #pragma unroll
                for (int h = 0; h < NH; h++) acc[h] = 0.f;
                #pragma unroll 4
                for (int j = 0; j < SPLITROWS; j++) {
                    float v = s_ckvp[j][c];
                    float4 p0 = *(const float4*)&s_sc[j * NH + 0];
                    float4 p1 = *(const float4*)&s_sc[j * NH + 4];
                    float4 p2 = *(const float4*)&s_sc[j * NH + 8];
                    float4 p3 = *(const float4*)&s_sc[j * NH + 12];
                    acc[0]  += p0.x * v; acc[1]  += p0.y * v; acc[2]  += p0.z * v; acc[3]  += p0.w * v;
                    acc[4]  += p1.x * v; acc[5]  += p1.y * v; acc[6]  += p1.z * v; acc[7]  += p1.w * v;
                    acc[8]  += p2.x * v; acc[9]  += p2.y * v; acc[10] += p2.z * v; acc[11] += p2.w * v;
                    acc[12] += p3.x * v; acc[13] += p3.y * v; acc[14] += p3.z * v; acc[15] += p3.w * v;
                }
                #pragma unroll
                for (int h = 0; h < NH; h++) g_op[b][s][h][c] = acc[h];
            }
            __syncthreads();
        }
    }
    gsync(6, nb);

    // ===== P6: combine + output projection =====
    {
        float* s_olat = (float*)sm_raw;
        float* s_w    = (float*)(sm_raw + 2048);
        float* s_invl = (float*)(sm_raw + 2112);
        for (int u = bx; u < NH * BS; u += nb) {
            int h = u & 15, b = u >> 4;
            if (tid == 0) {
                float M = -1e30f;
                for (int s = 0; s < NSPLIT; s++) M = fmaxf(M, g_m[b][s][h]);
                float L = 0.f;
                for (int s = 0; s < NSPLIT; s++) {
                    float w = __expf(g_m[b][s][h] - M);
                    s_w[s] = w;
                    L += g_l[b][s][h] * w;
                }
                *s_invl = 1.f / L;
            }
            __syncthreads();
            for (int c = tid; c < KVL; c += 256) {
                float a = 0.f;
                #pragma unroll
                for (int s = 0; s < NSPLIT; s++) a += g_op[b][s][h][c] * s_w[s];
                s_olat[c] = a * (*s_invl);
            }
            __syncthreads();
            if (tid < DN) {
                int d = tid;
                const float* wk = w_uk + ((size_t)(h * DN + d)) * KVL;
                float a = 0.f;
                #pragma unroll 8
                for (int c = 0; c < KVL; c += 4) {
                    float4 o4 = *(const float4*)&s_olat[c];
                    float4 w4 = *(const float4*)&wk[c];
                    a += o4.x * w4.x + o4.y * w4.y + o4.z * w4.z + o4.w * w4.w;
                }
                out[b * (NH * DN) + h * DN + d] = a;
            }
            __syncthreads();
        }
    }

    // reset barrier state for next graph replay
    __syncthreads();
    if (tid == 0) {
        __threadfence();
        unsigned a = atomicAdd(&g_ack, 1u) + 1;
        if (a == (unsigned)nb) {
            #pragma unroll
            for (int i = 0; i < 16; i++) g_barcnt[i] = 0;
            g_ack = 0;
            __threadfence();
        }
    }
}

// ---------------- launch ----------------
extern "C" void kernel_launch(void* const* d_in, const int* in_sizes, int n_in,
                              void* d_out, int out_size) {
    const float* x            = (const float*)d_in[0];
    const float* w_dq         = (const float*)d_in[1];
    const float* w_uq_qr      = (const float*)d_in[2];
    const float* w_uk         = (const float*)d_in[3];
    const float* w_dkv_kr     = (const float*)d_in[4];
    const float* gamma_cq     = (const float*)d_in[5];
    const float* gamma_ckv    = (const float*)d_in[6];
    const float* sinp         = (const float*)d_in[7];
    const float* cosp         = (const float*)d_in[8];
    const int*   cache_index  = (const int*)d_in[9];
    const float* kv_cache     = (const float*)d_in[10];
    const float* kr_cache     = (const float*)d_in[11];
    const int*   block_table  = (const int*)d_in[12];
    const int*   act_seqs     = (const int*)d_in[13];
    const float* w_idx_qb     = (const float*)d_in[14];
    const float* w_idx_k      = (const float*)d_in[15];
    const float* w_idx_proj   = (const float*)d_in[16];
    const float* in_gamma_k   = (const float*)d_in[17];
    const float* in_beta_k    = (const float*)d_in[18];
    const float* index_k_cache= (const float*)d_in[19];
    float* out = (float*)d_out;

    int sms = 148, bpm = 0;
    cudaDeviceGetAttribute(&sms, cudaDevAttrMultiProcessorCount, 0);
    cudaOccupancyMaxActiveBlocksPerMultiprocessor(&bpm, k_mega, 256, 0);
    if (bpm < 1) bpm = 1;
    int nb = bpm * sms;
    if (nb > NBMAX) nb = NBMAX;

    k_mega<<<nb, 256>>>(x, w_dq, w_uq_qr, w_uk, w_dkv_kr, gamma_cq, gamma_ckv,
                        sinp, cosp, cache_index, kv_cache, kr_cache, block_table,
                        act_seqs, w_idx_qb, w_idx_k, w_idx_proj, in_gamma_k,
                        in_beta_k, index_k_cache, out, nb);
}